// round 7
// baseline (speedup 1.0000x reference)
#include <cuda_runtime.h>
#include <cuda_bf16.h>
#include <math_constants.h>
#include <cstdint>

// Problem constants
#define B_   16
#define L_   1024
#define D_   128
#define H_   8
#define HD_  16
#define ROWS (B_ * L_)          // 16384
#define LN_EPS 1e-5f
#define NMASKW (B_ * L_ * L_ / 32)

// ---------------- scratch (device globals) ---------------------------------
__device__ float g_q  [ROWS * D_];
__device__ __nv_bfloat16 g_kh[ROWS * D_];
__device__ __nv_bfloat16 g_kl[ROWS * D_];
__device__ __nv_bfloat16 g_vh[ROWS * D_];
__device__ __nv_bfloat16 g_xh[ROWS * D_];
__device__ __nv_bfloat16 g_xl[ROWS * D_];
__device__ __nv_bfloat16 g_wqh[D_ * 3 * D_];
__device__ __nv_bfloat16 g_wql[D_ * 3 * D_];
__device__ __nv_bfloat16 g_w1h[D_ * D_];
__device__ __nv_bfloat16 g_w1l[D_ * D_];
__device__ __nv_bfloat16 g_w2h[D_ * D_];
__device__ __nv_bfloat16 g_w2l[D_ * D_];
__device__ __nv_bfloat16 g_f1h[ROWS * D_];
__device__ __nv_bfloat16 g_f1l[ROWS * D_];
__device__ __nv_bfloat16 g_x1h[ROWS * D_];
__device__ __nv_bfloat16 g_x1l[ROWS * D_];
__device__ float g_po0[ROWS * D_];
__device__ float g_po1[ROWS * D_];
__device__ float g_pl [2 * ROWS * H_];
__device__ float g_x1 [ROWS * D_];
__device__ uint32_t g_maskbits[NMASKW];
__device__ int g_mask_is_i32;

// ============================ helpers ======================================
__device__ __forceinline__ uint32_t smem_u32(const void* p) {
    uint32_t a;
    asm("{ .reg .u64 t; cvta.to.shared.u64 t, %1; cvt.u32.u64 %0, t; }"
        : "=r"(a) : "l"(p));
    return a;
}
__device__ __forceinline__ uint32_t pack_bf16x2(float e, float o) {
    uint32_t r;
    asm("cvt.rn.bf16x2.f32 %0, %1, %2;" : "=r"(r) : "f"(o), "f"(e));
    return r;
}
__device__ __forceinline__ float ex2f(float x) {
    float y; asm("ex2.approx.f32 %0, %1;" : "=f"(y) : "f"(x)); return y;
}
__device__ __forceinline__ float bfr(float x) {
    return __bfloat162float(__float2bfloat16_rn(x));
}
__device__ __forceinline__ void mma_bf16(float* c, const uint32_t* a, uint32_t b0, uint32_t b1) {
    asm volatile("mma.sync.aligned.m16n8k16.row.col.f32.bf16.bf16.f32 "
        "{%0,%1,%2,%3}, {%4,%5,%6,%7}, {%8,%9}, {%0,%1,%2,%3};"
        : "+f"(c[0]), "+f"(c[1]), "+f"(c[2]), "+f"(c[3])
        : "r"(a[0]), "r"(a[1]), "r"(a[2]), "r"(a[3]), "r"(b0), "r"(b1));
}
__device__ __forceinline__ void ldm_x4(uint32_t* r, uint32_t addr) {
    asm volatile("ldmatrix.sync.aligned.m8n8.x4.shared.b16 {%0,%1,%2,%3}, [%4];"
        : "=r"(r[0]), "=r"(r[1]), "=r"(r[2]), "=r"(r[3]) : "r"(addr));
}
__device__ __forceinline__ void ldm_x4_t(uint32_t* r, uint32_t addr) {
    asm volatile("ldmatrix.sync.aligned.m8n8.x4.trans.shared.b16 {%0,%1,%2,%3}, [%4];"
        : "=r"(r[0]), "=r"(r[1]), "=r"(r[2]), "=r"(r[3]) : "r"(addr));
}
#define ONES2 0x3F803F80u

// ---------------- mask detect + bitpack + fp32->bf16 hi/lo conv ------------
__global__ void detect_mask_kernel(const unsigned char* __restrict__ m) {
    if (threadIdx.x == 0 && blockIdx.x == 0) {
        int i32like = 1;
        for (int i = 0; i < 4096; i += 4) {
            unsigned char b0 = m[i], b1 = m[i+1], b2 = m[i+2], b3 = m[i+3];
            if ((b1 | b2 | b3) != 0 || b0 > 1) { i32like = 0; break; }
        }
        g_mask_is_i32 = i32like;
    }
}
__global__ void maskbits_kernel(const void* __restrict__ in) {
    int wIdx = blockIdx.x * blockDim.x + threadIdx.x;
    if (wIdx >= NMASKW) return;
    uint32_t bits = 0;
    if (g_mask_is_i32) {
        const int* p = (const int*)in + (size_t)wIdx * 32;
        #pragma unroll
        for (int j = 0; j < 32; j++) bits |= (p[j] != 0 ? 1u : 0u) << j;
    } else {
        const uint4* p = (const uint4*)((const uint8_t*)in + (size_t)wIdx * 32);
        uint4 a = p[0], bq = p[1];
        uint32_t ww[8] = {a.x, a.y, a.z, a.w, bq.x, bq.y, bq.z, bq.w};
        #pragma unroll
        for (int u = 0; u < 8; u++)
            #pragma unroll
            for (int j = 0; j < 4; j++)
                bits |= (((ww[u] >> (8 * j)) & 0xFFu) ? 1u : 0u) << (u * 4 + j);
    }
    g_maskbits[wIdx] = bits;
}
__global__ void conv_kernel(const float* __restrict__ src,
                            __nv_bfloat16* __restrict__ dh,
                            __nv_bfloat16* __restrict__ dl, int n) {
    int i = blockIdx.x * blockDim.x + threadIdx.x;
    if (i >= n) return;
    float f = src[i];
    float h = bfr(f);
    dh[i] = __float2bfloat16_rn(h);
    dl[i] = __float2bfloat16_rn(f - h);
}

// ================= HMMA GEMM (pre-converted bf16 planes) ===================
// mode 1: relu(A@B + bias) -> Ch/Cl planes (N=128)
// mode 2: QKV: n0==0 -> Cf fp32 Q; n0==128 -> Ch/Cl K; n0==256 -> Cv V hi
__global__ __launch_bounds__(256) void hmma_gemm_pre(
    const __nv_bfloat16* __restrict__ Ah, const __nv_bfloat16* __restrict__ Al,
    const __nv_bfloat16* __restrict__ Bh, const __nv_bfloat16* __restrict__ Bl,
    const float* __restrict__ bias, int N, int mode,
    float* __restrict__ Cf,
    __nv_bfloat16* __restrict__ Ch, __nv_bfloat16* __restrict__ Cl,
    __nv_bfloat16* __restrict__ Cv)
{
    __shared__ __align__(16) uint8_t sAh[64 * 128];
    __shared__ __align__(16) uint8_t sAl[64 * 128];
    __shared__ __align__(16) uint8_t sBh[2][64 * 128];
    __shared__ __align__(16) uint8_t sBl[2][64 * 128];

    const int tid  = threadIdx.x;
    const int lane = tid & 31;
    const int w    = tid >> 5;
    const int wm   = w & 3;
    const int wn   = w >> 2;
    const int m0   = blockIdx.y * 64;
    const int n0   = blockIdx.x * 128;

    const int rq = lane >> 2;
    const int d0 = (lane & 3) * 2;
    const int lr16  = lane & 15;
    const int lclog = lane >> 4;
    const int lm = lane >> 3, lr = lane & 7;

    float c[8][4];
    #pragma unroll
    for (int i = 0; i < 8; i++)
        #pragma unroll
        for (int j = 0; j < 4; j++) c[i][j] = 0.f;

    const uint32_t aAh = smem_u32(sAh);
    const uint32_t aAl = smem_u32(sAl);
    const uint32_t aBh = smem_u32(sBh[wn]);
    const uint32_t aBl = smem_u32(sBl[wn]);

    #pragma unroll
    for (int khalf = 0; khalf < 2; ++khalf) {
        __syncthreads();
        #pragma unroll
        for (int rep = 0; rep < 2; ++rep) {
            int idx = rep * 256 + tid;
            int row = idx >> 3, chunk = idx & 7;
            uint32_t off = (uint32_t)(row * 128) + (((uint32_t)(chunk ^ (row & 7))) << 4);
            const uint4* sh = (const uint4*)(Ah + (size_t)(m0 + row) * 128 + khalf * 64);
            const uint4* sl = (const uint4*)(Al + (size_t)(m0 + row) * 128 + khalf * 64);
            *(uint4*)(sAh + off) = sh[chunk];
            *(uint4*)(sAl + off) = sl[chunk];
        }
        #pragma unroll
        for (int rep = 0; rep < 4; ++rep) {
            int idx = rep * 256 + tid;
            int nh = idx >> 9, kr = (idx >> 3) & 63, chunk = idx & 7;
            uint32_t off = (uint32_t)(kr * 128) + (((uint32_t)(chunk ^ (kr & 7))) << 4);
            const uint4* sh = (const uint4*)(Bh + (size_t)(khalf * 64 + kr) * N + n0 + nh * 64);
            const uint4* sl = (const uint4*)(Bl + (size_t)(khalf * 64 + kr) * N + n0 + nh * 64);
            *(uint4*)(sBh[nh] + off) = sh[chunk];
            *(uint4*)(sBl[nh] + off) = sl[chunk];
        }
        __syncthreads();

        #pragma unroll
        for (int s = 0; s < 4; ++s) {
            uint32_t ah[4], al[4];
            {
                int row = wm * 16 + lr16;
                uint32_t off = (uint32_t)(row * 128) + ((((uint32_t)(s * 2 + lclog) ^ (row & 7)) << 4));
                ldm_x4(ah, aAh + off);
                ldm_x4(al, aAl + off);
            }
            int rowB = s * 16 + ((lm & 1) << 3) + lr;
            uint32_t rbase = (uint32_t)(rowB * 128);
            #pragma unroll
            for (int g = 0; g < 4; ++g) {
                uint32_t chunk = (uint32_t)(g * 2 + (lm >> 1));
                uint32_t off = rbase + ((chunk ^ (rowB & 7)) << 4);
                uint32_t bh[4], bl[4];
                ldm_x4_t(bh, aBh + off);
                ldm_x4_t(bl, aBl + off);
                mma_bf16(c[g*2],   ah, bh[0], bh[1]);
                mma_bf16(c[g*2],   ah, bl[0], bl[1]);
                mma_bf16(c[g*2],   al, bh[0], bh[1]);
                mma_bf16(c[g*2+1], ah, bh[2], bh[3]);
                mma_bf16(c[g*2+1], ah, bl[2], bl[3]);
                mma_bf16(c[g*2+1], al, bh[2], bh[3]);
            }
        }
    }

    const int rowA = m0 + wm * 16 + rq;
    #pragma unroll
    for (int t8 = 0; t8 < 8; ++t8) {
        int col = n0 + wn * 64 + t8 * 8 + d0;
        float b0 = bias[col], b1 = bias[col + 1];
        float v00 = c[t8][0] + b0, v01 = c[t8][1] + b1;
        float v10 = c[t8][2] + b0, v11 = c[t8][3] + b1;

        if (mode == 1) {
            v00 = fmaxf(v00, 0.f); v01 = fmaxf(v01, 0.f);
            v10 = fmaxf(v10, 0.f); v11 = fmaxf(v11, 0.f);
            float h00 = bfr(v00), h01 = bfr(v01), h10 = bfr(v10), h11 = bfr(v11);
            ((uint32_t*)Ch)[((size_t)rowA * 128 + col) >> 1]       = pack_bf16x2(h00, h01);
            ((uint32_t*)Cl)[((size_t)rowA * 128 + col) >> 1]       = pack_bf16x2(v00 - h00, v01 - h01);
            ((uint32_t*)Ch)[((size_t)(rowA + 8) * 128 + col) >> 1] = pack_bf16x2(h10, h11);
            ((uint32_t*)Cl)[((size_t)(rowA + 8) * 128 + col) >> 1] = pack_bf16x2(v10 - h10, v11 - h11);
        } else {
            if (n0 == 0) {
                *(float2*)(Cf + (size_t)rowA * 128 + col)       = make_float2(v00, v01);
                *(float2*)(Cf + (size_t)(rowA + 8) * 128 + col) = make_float2(v10, v11);
            } else if (n0 == 128) {
                int kc = col - 128;
                float h00 = bfr(v00), h01 = bfr(v01), h10 = bfr(v10), h11 = bfr(v11);
                ((uint32_t*)Ch)[((size_t)rowA * 128 + kc) >> 1]       = pack_bf16x2(h00, h01);
                ((uint32_t*)Cl)[((size_t)rowA * 128 + kc) >> 1]       = pack_bf16x2(v00 - h00, v01 - h01);
                ((uint32_t*)Ch)[((size_t)(rowA + 8) * 128 + kc) >> 1] = pack_bf16x2(h10, h11);
                ((uint32_t*)Cl)[((size_t)(rowA + 8) * 128 + kc) >> 1] = pack_bf16x2(v10 - h10, v11 - h11);
            } else {
                int vc = col - 256;
                ((uint32_t*)Cv)[((size_t)rowA * 128 + vc) >> 1]       = pack_bf16x2(bfr(v00), bfr(v01));
                ((uint32_t*)Cv)[((size_t)(rowA + 8) * 128 + vc) >> 1] = pack_bf16x2(bfr(v10), bfr(v11));
            }
        }
    }
}

// ============ fused ff2 GEMM + residual add + LayerNorm (N=128) ============
// out = LN(xin + A@B + bias) ; block owns 64 complete rows.
#define SA_H 0
#define SA_L 8192
#define SB_H 16384
#define SB_L 32768
__global__ __launch_bounds__(256) void hmma_gemm_ln(
    const __nv_bfloat16* __restrict__ Ah, const __nv_bfloat16* __restrict__ Al,
    const __nv_bfloat16* __restrict__ Bh, const __nv_bfloat16* __restrict__ Bl,
    const float* __restrict__ bias, const float* __restrict__ xin,
    const float* __restrict__ gamma, const float* __restrict__ beta,
    float* __restrict__ out)
{
    __shared__ __align__(16) uint8_t sbuf[49152];

    const int tid  = threadIdx.x;
    const int lane = tid & 31;
    const int w    = tid >> 5;
    const int wm   = w & 3;
    const int wn   = w >> 2;
    const int m0   = blockIdx.y * 64;

    const int rq = lane >> 2;
    const int d0 = (lane & 3) * 2;
    const int lr16  = lane & 15;
    const int lclog = lane >> 4;
    const int lm = lane >> 3, lr = lane & 7;

    float c[8][4];
    #pragma unroll
    for (int i = 0; i < 8; i++)
        #pragma unroll
        for (int j = 0; j < 4; j++) c[i][j] = 0.f;

    const uint32_t aAh = smem_u32(sbuf + SA_H);
    const uint32_t aAl = smem_u32(sbuf + SA_L);
    const uint32_t aBh = smem_u32(sbuf + SB_H + wn * 8192);
    const uint32_t aBl = smem_u32(sbuf + SB_L + wn * 8192);

    #pragma unroll
    for (int khalf = 0; khalf < 2; ++khalf) {
        __syncthreads();
        #pragma unroll
        for (int rep = 0; rep < 2; ++rep) {
            int idx = rep * 256 + tid;
            int row = idx >> 3, chunk = idx & 7;
            uint32_t off = (uint32_t)(row * 128) + (((uint32_t)(chunk ^ (row & 7))) << 4);
            const uint4* sh = (const uint4*)(Ah + (size_t)(m0 + row) * 128 + khalf * 64);
            const uint4* sl = (const uint4*)(Al + (size_t)(m0 + row) * 128 + khalf * 64);
            *(uint4*)(sbuf + SA_H + off) = sh[chunk];
            *(uint4*)(sbuf + SA_L + off) = sl[chunk];
        }
        #pragma unroll
        for (int rep = 0; rep < 4; ++rep) {
            int idx = rep * 256 + tid;
            int nh = idx >> 9, kr = (idx >> 3) & 63, chunk = idx & 7;
            uint32_t off = (uint32_t)(kr * 128) + (((uint32_t)(chunk ^ (kr & 7))) << 4);
            const uint4* sh = (const uint4*)(Bh + (size_t)(khalf * 64 + kr) * 128 + nh * 64);
            const uint4* sl = (const uint4*)(Bl + (size_t)(khalf * 64 + kr) * 128 + nh * 64);
            *(uint4*)(sbuf + SB_H + nh * 8192 + off) = sh[chunk];
            *(uint4*)(sbuf + SB_L + nh * 8192 + off) = sl[chunk];
        }
        __syncthreads();

        #pragma unroll
        for (int s = 0; s < 4; ++s) {
            uint32_t ah[4], al[4];
            {
                int row = wm * 16 + lr16;
                uint32_t off = (uint32_t)(row * 128) + ((((uint32_t)(s * 2 + lclog) ^ (row & 7)) << 4));
                ldm_x4(ah, aAh + off);
                ldm_x4(al, aAl + off);
            }
            int rowB = s * 16 + ((lm & 1) << 3) + lr;
            uint32_t rbase = (uint32_t)(rowB * 128);
            #pragma unroll
            for (int g = 0; g < 4; ++g) {
                uint32_t chunk = (uint32_t)(g * 2 + (lm >> 1));
                uint32_t off = rbase + ((chunk ^ (rowB & 7)) << 4);
                uint32_t bh[4], bl[4];
                ldm_x4_t(bh, aBh + off);
                ldm_x4_t(bl, aBl + off);
                mma_bf16(c[g*2],   ah, bh[0], bh[1]);
                mma_bf16(c[g*2],   ah, bl[0], bl[1]);
                mma_bf16(c[g*2],   al, bh[0], bh[1]);
                mma_bf16(c[g*2+1], ah, bh[2], bh[3]);
                mma_bf16(c[g*2+1], ah, bl[2], bl[3]);
                mma_bf16(c[g*2+1], al, bh[2], bh[3]);
            }
        }
    }

    // ---- write GEMM results (+bias) into smem sC (overlays staging) --------
    __syncthreads();
    float* sC = (float*)sbuf;                 // 64 x 128 fp32 = 32 KB
    {
        const int rowT = wm * 16 + rq;
        #pragma unroll
        for (int t8 = 0; t8 < 8; ++t8) {
            int col = wn * 64 + t8 * 8 + d0;
            float b0 = bias[col], b1 = bias[col + 1];
            sC[rowT * 128 + col]           = c[t8][0] + b0;
            sC[rowT * 128 + col + 1]       = c[t8][1] + b1;
            sC[(rowT + 8) * 128 + col]     = c[t8][2] + b0;
            sC[(rowT + 8) * 128 + col + 1] = c[t8][3] + b1;
        }
    }
    __syncthreads();

    // ---- LayerNorm: 4 threads per row, 32 cols each -------------------------
    {
        const int row = tid >> 2;
        const int q4 = tid & 3;
        float* vr = sC + row * 128 + q4 * 32;
        const float* xr = xin + (size_t)(m0 + row) * 128 + q4 * 32;

        float s = 0.f;
        #pragma unroll
        for (int j = 0; j < 32; j++) {
            float v = vr[j] + xr[j];
            vr[j] = v;
            s += v;
        }
        s += __shfl_xor_sync(0xffffffffu, s, 1);
        s += __shfl_xor_sync(0xffffffffu, s, 2);
        float mu = s * (1.f / 128.f);

        float q = 0.f;
        #pragma unroll
        for (int j = 0; j < 32; j++) {
            float d = vr[j] - mu;
            q += d * d;
        }
        q += __shfl_xor_sync(0xffffffffu, q, 1);
        q += __shfl_xor_sync(0xffffffffu, q, 2);
        float rs = rsqrtf(q * (1.f / 128.f) + LN_EPS);

        float* orow = out + (size_t)(m0 + row) * 128 + q4 * 32;
        #pragma unroll
        for (int j = 0; j < 32; j++) {
            orow[j] = (vr[j] - mu) * rs * gamma[q4 * 32 + j] + beta[q4 * 32 + j];
        }
    }
}

// ================= HMMA flash attention (8 warps, NT=1, key-split) =========
#define KROWB 48

__global__ __launch_bounds__(256) void attn_mma_kernel(
    float* __restrict__ po0, float* __restrict__ po1, float* __restrict__ pl)
{
    __shared__ __align__(16) uint8_t sKh[128 * KROWB];
    __shared__ __align__(16) uint8_t sKl[128 * KROWB];
    __shared__ __align__(16) uint8_t sVh[128 * KROWB];

    const int tid  = threadIdx.x;
    const int lane = tid & 31;
    const int w    = tid >> 5;         // 0..7, warp owns q rows w*16..+15
    const int b    = blockIdx.y >> 3;
    const int h    = blockIdx.y & 7;
    const int q0   = blockIdx.x << 7;
    const int zz   = blockIdx.z;

    const int rq = lane >> 2;
    const int d0 = (lane & 3) * 2;

    const float qscale = 0.25f * 1.44269504088896f;

    // ---- Q fragment (hi/lo bf16 split) from fp32 Q plane --------------------
    uint32_t ah[4], al[4];
    {
        int rowA = q0 + w * 16 + rq;
        const float* qb = g_q + (size_t)(b * L_ + rowA) * D_ + h * HD_;
        float2 e0 = *(const float2*)(qb + d0);
        float2 e1 = *(const float2*)(qb + (size_t)8 * D_ + d0);
        float2 e2 = *(const float2*)(qb + d0 + 8);
        float2 e3 = *(const float2*)(qb + (size_t)8 * D_ + d0 + 8);
        float v[8] = {e0.x * qscale, e0.y * qscale, e1.x * qscale, e1.y * qscale,
                      e2.x * qscale, e2.y * qscale, e3.x * qscale, e3.y * qscale};
        #pragma unroll
        for (int j = 0; j < 4; j++) {
            float hx = bfr(v[2*j]), hy = bfr(v[2*j+1]);
            ah[j] = pack_bf16x2(hx, hy);
            al[j] = pack_bf16x2(v[2*j] - hx, v[2*j+1] - hy);
        }
    }

    const uint4* mbase = (const uint4*)g_maskbits;
    const int mrowA = (b * L_ + q0 + w * 16 + rq) * 8;
    const int mrowB = mrowA + 8 * 8;

    const int lm = lane >> 3, lr = lane & 7;
    const uint32_t kOff = (uint32_t)((((lm >> 1) << 3) + lr) * KROWB + ((lm & 1) << 4));
    const uint32_t vOff = (uint32_t)((((lm & 1) << 3) + lr) * KROWB + ((lm >> 1) << 4));
    const uint32_t aKh = smem_u32(sKh) + kOff;
    const uint32_t aKl = smem_u32(sKl) + kOff;
    const uint32_t aVh = smem_u32(sVh) + vOff;

    float o[2][4];
    float lac[4];
    #pragma unroll
    for (int n = 0; n < 2; n++)
        #pragma unroll
        for (int i = 0; i < 4; i++) o[n][i] = 0.f;
    #pragma unroll
    for (int i = 0; i < 4; i++) lac[i] = 0.f;

    for (int ck = zz * 4; ck < zz * 4 + 4; ++ck) {
        const int c0 = ck << 7;

        __syncthreads();
        // ---- stage K/V: 256 threads; 0-127 K hi/lo, 128-255 V hi ------------
        if (tid < 128) {
            const size_t src = (size_t)(b * L_ + c0 + tid) * D_ + h * HD_;
            const uint4* kh = (const uint4*)(g_kh + src);
            const uint4* kl = (const uint4*)(g_kl + src);
            uint4* dkh = (uint4*)(sKh + tid * KROWB);
            uint4* dkl = (uint4*)(sKl + tid * KROWB);
            dkh[0] = kh[0]; dkh[1] = kh[1];
            dkl[0] = kl[0]; dkl[1] = kl[1];
        } else {
            const int r = tid - 128;
            const size_t src = (size_t)(b * L_ + c0 + r) * D_ + h * HD_;
            const uint4* vh = (const uint4*)(g_vh + src);
            uint4* dvh = (uint4*)(sVh + r * KROWB);
            dvh[0] = vh[0]; dvh[1] = vh[1];
        }
        __syncthreads();

        uint32_t mwa[4], mwb[4];
        {
            uint4 a = mbase[mrowA + (c0 >> 7)];
            uint4 bq = mbase[mrowB + (c0 >> 7)];
            mwa[0] = a.x;  mwa[1] = a.y;  mwa[2] = a.z;  mwa[3] = a.w;
            mwb[0] = bq.x; mwb[1] = bq.y; mwb[2] = bq.z; mwb[3] = bq.w;
        }

        #pragma unroll
        for (int s = 0; s < 8; ++s) {
            const uint32_t so = (uint32_t)(s * 16 * KROWB);
            uint32_t kh[4], kl[4], vh[4];
            ldm_x4(kh, aKh + so);
            ldm_x4(kl, aKl + so);
            ldm_x4_t(vh, aVh + so);
            const int sh = ((s & 1) << 4) + d0;

            // split accumulators: chain depth 2, 4 parallel chains
            float cA0[4] = {0.f, 0.f, 0.f, 0.f};
            float cB0[4] = {0.f, 0.f, 0.f, 0.f};
            float cA1[4] = {0.f, 0.f, 0.f, 0.f};
            float cB1[4] = {0.f, 0.f, 0.f, 0.f};
            mma_bf16(cA0, ah, kh[0], kh[1]);
            mma_bf16(cB0, ah, kl[0], kl[1]);
            mma_bf16(cA1, ah, kh[2], kh[3]);
            mma_bf16(cB1, ah, kl[2], kl[3]);
            mma_bf16(cB0, al, kh[0], kh[1]);
            mma_bf16(cB1, al, kh[2], kh[3]);

            uint32_t wa = mwa[s >> 1] >> sh;
            uint32_t wb = mwb[s >> 1] >> sh;

            float p00 = (wa & 1u)     ? 0.f : ex2f(cA0[0] + cB0[0]);
            float p01 = (wa & 2u)     ? 0.f : ex2f(cA0[1] + cB0[1]);
            float p02 = (wb & 1u)     ? 0.f : ex2f(cA0[2] + cB0[2]);
            float p03 = (wb & 2u)     ? 0.f : ex2f(cA0[3] + cB0[3]);
            float p10 = (wa & 0x100u) ? 0.f : ex2f(cA1[0] + cB1[0]);
            float p11 = (wa & 0x200u) ? 0.f : ex2f(cA1[1] + cB1[1]);
            float p12 = (wb & 0x100u) ? 0.f : ex2f(cA1[2] + cB1[2]);
            float p13 = (wb & 0x200u) ? 0.f : ex2f(cA1[3] + cB1[3]);

            uint32_t ap[4];
            ap[0] = pack_bf16x2(p00, p01);
            ap[1] = pack_bf16x2(p02, p03);
            ap[2] = pack_bf16x2(p10, p11);
            ap[3] = pack_bf16x2(p12, p13);

            mma_bf16(o[0], ap, vh[0], vh[1]);
            mma_bf16(o[1], ap, vh[2], vh[3]);
            mma_bf16(lac, ap, ONES2, ONES2);
        }
    }

    // ---- epilogue: write partial O and l ------------------------------------
    float* po = zz ? po1 : po0;
    {
        int rowA = q0 + w * 16 + rq;
        float* oA = po + (size_t)(b * L_ + rowA) * D_ + h * HD_;
        float* oB = oA + (size_t)8 * D_;
        #pragma unroll
        for (int n = 0; n < 2; n++) {
            *(float2*)(oA + n * 8 + d0) = make_float2(o[n][0], o[n][1]);
            *(float2*)(oB + n * 8 + d0) = make_float2(o[n][2], o[n][3]);
        }
        if ((lane & 3) == 0) {
            pl[(size_t)zz * ROWS * H_ + (size_t)(b * L_ + rowA) * H_ + h]     = lac[0];
            pl[(size_t)zz * ROWS * H_ + (size_t)(b * L_ + rowA + 8) * H_ + h] = lac[2];
        }
    }
}

// ---------------- combine partials + residual add + LayerNorm --------------
__global__ __launch_bounds__(128) void combine_add_ln_kernel(
    const float* __restrict__ xin,
    const float* __restrict__ po0, const float* __restrict__ po1,
    const float* __restrict__ pl,
    const float* __restrict__ gamma, const float* __restrict__ beta,
    float* __restrict__ out,
    __nv_bfloat16* __restrict__ oh, __nv_bfloat16* __restrict__ ol)
{
    const int row = blockIdx.x;
    const int t = threadIdx.x;
    const int head = t >> 4;
    const int warp = t >> 5, lane = t & 31;
    __shared__ float red1[4], red2[4];

    float l = pl[(size_t)row * H_ + head] + pl[(size_t)ROWS * H_ + (size_t)row * H_ + head];
    float osum = po0[(size_t)row * D_ + t] + po1[(size_t)row * D_ + t];
    float v = xin[(size_t)row * D_ + t] + ((l > 0.f) ? (osum / l) : 0.f);

    float s = v;
    #pragma unroll
    for (int o = 16; o; o >>= 1) s += __shfl_xor_sync(0xffffffffu, s, o);
    if (lane == 0) red1[warp] = s;
    __syncthreads();
    float mu = (red1[0] + red1[1] + red1[2] + red1[3]) * (1.f / D_);

    float c = v - mu;
    float q = c * c;
    #pragma unroll
    for (int o = 16; o; o >>= 1) q += __shfl_xor_sync(0xffffffffu, q, o);
    if (lane == 0) red2[warp] = q;
    __syncthreads();
    float var = (red2[0] + red2[1] + red2[2] + red2[3]) * (1.f / D_);

    float y = c * rsqrtf(var + LN_EPS) * gamma[t] + beta[t];
    out[(size_t)row * D_ + t] = y;
    float hy = bfr(y);
    oh[(size_t)row * D_ + t] = __float2bfloat16_rn(hy);
    ol[(size_t)row * D_ + t] = __float2bfloat16_rn(y - hy);
}

// ---------------- launch --------------------------------------------------
extern "C" void kernel_launch(void* const* d_in, const int* in_sizes, int n_in,
                              void* d_out, int out_size)
{
    const float* edge_x    = (const float*)d_in[0];
    const void*  edge_mask = d_in[1];
    const float* in_proj_w = (const float*)d_in[2];
    const float* in_proj_b = (const float*)d_in[3];
    const float* w1        = (const float*)d_in[4];
    const float* b1        = (const float*)d_in[5];
    const float* w2        = (const float*)d_in[6];
    const float* b2        = (const float*)d_in[7];
    const float* g1        = (const float*)d_in[8];
    const float* beta1     = (const float*)d_in[9];
    const float* g2        = (const float*)d_in[10];
    const float* beta2     = (const float*)d_in[11];
    float* out = (float*)d_out;

    void *p_q, *p_kh, *p_kl, *p_vh, *p_xh, *p_xl;
    void *p_wqh, *p_wql, *p_w1h, *p_w1l, *p_w2h, *p_w2l;
    void *p_f1h, *p_f1l, *p_x1h, *p_x1l;
    void *p_po0, *p_po1, *p_pl, *p_x1;
    cudaGetSymbolAddress(&p_q,   g_q);
    cudaGetSymbolAddress(&p_kh,  g_kh);
    cudaGetSymbolAddress(&p_kl,  g_kl);
    cudaGetSymbolAddress(&p_vh,  g_vh);
    cudaGetSymbolAddress(&p_xh,  g_xh);
    cudaGetSymbolAddress(&p_xl,  g_xl);
    cudaGetSymbolAddress(&p_wqh, g_wqh);
    cudaGetSymbolAddress(&p_wql, g_wql);
    cudaGetSymbolAddress(&p_w1h, g_w1h);
    cudaGetSymbolAddress(&p_w1l, g_w1l);
    cudaGetSymbolAddress(&p_w2h, g_w2h);
    cudaGetSymbolAddress(&p_w2l, g_w2l);
    cudaGetSymbolAddress(&p_f1h, g_f1h);
    cudaGetSymbolAddress(&p_f1l, g_f1l);
    cudaGetSymbolAddress(&p_x1h, g_x1h);
    cudaGetSymbolAddress(&p_x1l, g_x1l);
    cudaGetSymbolAddress(&p_po0, g_po0);
    cudaGetSymbolAddress(&p_po1, g_po1);
    cudaGetSymbolAddress(&p_pl,  g_pl);
    cudaGetSymbolAddress(&p_x1,  g_x1);

    // 1) mask detect + bitpack
    detect_mask_kernel<<<1, 32>>>((const unsigned char*)edge_mask);
    maskbits_kernel<<<NMASKW / 256, 256>>>(edge_mask);

    // 2) pre-convert inputs/weights to bf16 hi/lo planes
    conv_kernel<<<ROWS * D_ / 256, 256>>>(edge_x, (__nv_bfloat16*)p_xh, (__nv_bfloat16*)p_xl, ROWS * D_);
    conv_kernel<<<(D_ * 3 * D_) / 256, 256>>>(in_proj_w, (__nv_bfloat16*)p_wqh, (__nv_bfloat16*)p_wql, D_ * 3 * D_);
    conv_kernel<<<(D_ * D_) / 256, 256>>>(w1, (__nv_bfloat16*)p_w1h, (__nv_bfloat16*)p_w1l, D_ * D_);
    conv_kernel<<<(D_ * D_) / 256, 256>>>(w2, (__nv_bfloat16*)p_w2h, (__nv_bfloat16*)p_w2l, D_ * D_);

    // 3) QKV projection (mode 2): Q fp32, K hi/lo, V hi
    {
        dim3 grid(3, ROWS / 64);
        hmma_gemm_pre<<<grid, 256>>>((const __nv_bfloat16*)p_xh, (const __nv_bfloat16*)p_xl,
                                     (const __nv_bfloat16*)p_wqh, (const __nv_bfloat16*)p_wql,
                                     in_proj_b, 3 * D_, 2,
                                     (float*)p_q, (__nv_bfloat16*)p_kh, (__nv_bfloat16*)p_kl,
                                     (__nv_bfloat16*)p_vh);
    }

    // 4) masked attention -> partial O, l (8 warps, NT=1)
    {
        dim3 grid(L_ / 128, B_ * H_, 2);
        attn_mma_kernel<<<grid, 256>>>((float*)p_po0, (float*)p_po1, (float*)p_pl);
    }

    // 5) x1 = LN(edge_x + combine(O,l)), emit fp32 + hi/lo planes
    combine_add_ln_kernel<<<ROWS, 128>>>(edge_x, (const float*)p_po0,
                                         (const float*)p_po1, (const float*)p_pl,
                                         g1, beta1, (float*)p_x1,
                                         (__nv_bfloat16*)p_x1h, (__nv_bfloat16*)p_x1l);

    // 6) ff1 = relu(x1 @ w1 + b1) -> hi/lo planes (mode 1)
    {
        dim3 grid(1, ROWS / 64);
        hmma_gemm_pre<<<grid, 256>>>((const __nv_bfloat16*)p_x1h, (const __nv_bfloat16*)p_x1l,
                                     (const __nv_bfloat16*)p_w1h, (const __nv_bfloat16*)p_w1l,
                                     b1, D_, 1,
                                     nullptr, (__nv_bfloat16*)p_f1h, (__nv_bfloat16*)p_f1l, nullptr);
    }
    // 7) out = LN(x1 + ff1 @ w2 + b2)  (fused GEMM + LN)
    {
        dim3 grid(1, ROWS / 64);
        hmma_gemm_ln<<<grid, 256>>>((const __nv_bfloat16*)p_f1h, (const __nv_bfloat16*)p_f1l,
                                    (const __nv_bfloat16*)p_w2h, (const __nv_bfloat16*)p_w2l,
                                    b2, (const float*)p_x1, g2, beta2, out);
    }
}

// round 8
// speedup vs baseline: 1.0274x; 1.0274x over previous
#include <cuda_runtime.h>
#include <cuda_bf16.h>
#include <math_constants.h>
#include <cstdint>

// Problem constants
#define B_   16
#define L_   1024
#define D_   128
#define H_   8
#define HD_  16
#define ROWS (B_ * L_)          // 16384
#define LN_EPS 1e-5f
#define NMASKW (B_ * L_ * L_ / 32)

// ---------------- scratch (device globals) ---------------------------------
__device__ float g_q  [ROWS * D_];
__device__ __nv_bfloat16 g_kh[ROWS * D_];
__device__ __nv_bfloat16 g_kl[ROWS * D_];
__device__ __nv_bfloat16 g_vh[ROWS * D_];
__device__ __nv_bfloat16 g_xh[ROWS * D_];
__device__ __nv_bfloat16 g_xl[ROWS * D_];
__device__ __nv_bfloat16 g_wqh[D_ * 3 * D_];
__device__ __nv_bfloat16 g_wql[D_ * 3 * D_];
__device__ __nv_bfloat16 g_w1h[D_ * D_];
__device__ __nv_bfloat16 g_w1l[D_ * D_];
__device__ __nv_bfloat16 g_w2h[D_ * D_];
__device__ __nv_bfloat16 g_w2l[D_ * D_];
__device__ __nv_bfloat16 g_f1h[ROWS * D_];
__device__ __nv_bfloat16 g_f1l[ROWS * D_];
__device__ __nv_bfloat16 g_x1h[ROWS * D_];
__device__ __nv_bfloat16 g_x1l[ROWS * D_];
__device__ float g_po0[ROWS * D_];
__device__ float g_po1[ROWS * D_];
__device__ float g_pl [2 * ROWS * H_];
__device__ float g_x1 [ROWS * D_];
__device__ uint32_t g_maskbits[NMASKW];
__device__ int g_mask_is_i32;

// ============================ helpers ======================================
__device__ __forceinline__ uint32_t smem_u32(const void* p) {
    uint32_t a;
    asm("{ .reg .u64 t; cvta.to.shared.u64 t, %1; cvt.u32.u64 %0, t; }"
        : "=r"(a) : "l"(p));
    return a;
}
__device__ __forceinline__ uint32_t pack_bf16x2(float e, float o) {
    uint32_t r;
    asm("cvt.rn.bf16x2.f32 %0, %1, %2;" : "=r"(r) : "f"(o), "f"(e));
    return r;
}
__device__ __forceinline__ float ex2f(float x) {
    float y; asm("ex2.approx.f32 %0, %1;" : "=f"(y) : "f"(x)); return y;
}
__device__ __forceinline__ float bfr(float x) {
    return __bfloat162float(__float2bfloat16_rn(x));
}
__device__ __forceinline__ void mma_bf16(float* c, const uint32_t* a, uint32_t b0, uint32_t b1) {
    asm volatile("mma.sync.aligned.m16n8k16.row.col.f32.bf16.bf16.f32 "
        "{%0,%1,%2,%3}, {%4,%5,%6,%7}, {%8,%9}, {%0,%1,%2,%3};"
        : "+f"(c[0]), "+f"(c[1]), "+f"(c[2]), "+f"(c[3])
        : "r"(a[0]), "r"(a[1]), "r"(a[2]), "r"(a[3]), "r"(b0), "r"(b1));
}
__device__ __forceinline__ void ldm_x4(uint32_t* r, uint32_t addr) {
    asm volatile("ldmatrix.sync.aligned.m8n8.x4.shared.b16 {%0,%1,%2,%3}, [%4];"
        : "=r"(r[0]), "=r"(r[1]), "=r"(r[2]), "=r"(r[3]) : "r"(addr));
}
__device__ __forceinline__ void ldm_x4_t(uint32_t* r, uint32_t addr) {
    asm volatile("ldmatrix.sync.aligned.m8n8.x4.trans.shared.b16 {%0,%1,%2,%3}, [%4];"
        : "=r"(r[0]), "=r"(r[1]), "=r"(r[2]), "=r"(r[3]) : "r"(addr));
}
__device__ __forceinline__ void cp16(uint32_t dst, const void* src) {
    asm volatile("cp.async.cg.shared.global [%0], [%1], 16;"
        :: "r"(dst), "l"(src) : "memory");
}
#define CP_COMMIT() asm volatile("cp.async.commit_group;" ::: "memory")
#define ONES2 0x3F803F80u

// ---------------- mask detect + bitpack + conversions ----------------------
__global__ void detect_mask_kernel(const unsigned char* __restrict__ m) {
    if (threadIdx.x == 0 && blockIdx.x == 0) {
        int i32like = 1;
        for (int i = 0; i < 4096; i += 4) {
            unsigned char b0 = m[i], b1 = m[i+1], b2 = m[i+2], b3 = m[i+3];
            if ((b1 | b2 | b3) != 0 || b0 > 1) { i32like = 0; break; }
        }
        g_mask_is_i32 = i32like;
    }
}
__global__ void maskbits_kernel(const void* __restrict__ in) {
    int wIdx = blockIdx.x * blockDim.x + threadIdx.x;
    if (wIdx >= NMASKW) return;
    uint32_t bits = 0;
    if (g_mask_is_i32) {
        const int* p = (const int*)in + (size_t)wIdx * 32;
        #pragma unroll
        for (int j = 0; j < 32; j++) bits |= (p[j] != 0 ? 1u : 0u) << j;
    } else {
        const uint4* p = (const uint4*)((const uint8_t*)in + (size_t)wIdx * 32);
        uint4 a = p[0], bq = p[1];
        uint32_t ww[8] = {a.x, a.y, a.z, a.w, bq.x, bq.y, bq.z, bq.w};
        #pragma unroll
        for (int u = 0; u < 8; u++)
            #pragma unroll
            for (int j = 0; j < 4; j++)
                bits |= (((ww[u] >> (8 * j)) & 0xFFu) ? 1u : 0u) << (u * 4 + j);
    }
    g_maskbits[wIdx] = bits;
}
__global__ void conv_kernel(const float* __restrict__ src,
                            __nv_bfloat16* __restrict__ dh,
                            __nv_bfloat16* __restrict__ dl, int n) {
    int i = blockIdx.x * blockDim.x + threadIdx.x;
    if (i >= n) return;
    float f = src[i];
    float h = bfr(f);
    dh[i] = __float2bfloat16_rn(h);
    dl[i] = __float2bfloat16_rn(f - h);
}
// all three weight matrices in one launch (81920 elements)
__global__ void conv_weights_kernel(const float* __restrict__ wq,
                                    const float* __restrict__ w1,
                                    const float* __restrict__ w2) {
    int i = blockIdx.x * blockDim.x + threadIdx.x;
    const float* src; __nv_bfloat16 *dh, *dl; int j;
    if (i < 49152)      { src = wq; dh = g_wqh; dl = g_wql; j = i; }
    else if (i < 65536) { src = w1; dh = g_w1h; dl = g_w1l; j = i - 49152; }
    else                { src = w2; dh = g_w2h; dl = g_w2l; j = i - 65536; }
    float f = src[j];
    float h = bfr(f);
    dh[j] = __float2bfloat16_rn(h);
    dl[j] = __float2bfloat16_rn(f - h);
}

// ================= HMMA GEMM BM=32 (pre-converted bf16 planes) =============
// 256 threads = 8 warps: wm = w&1 (m16 tile), wn = w>>1 (n32 group).
// mode 1: relu(A@B + bias) -> Ch/Cl planes (N=128)
// mode 2: QKV: n0==0 -> Cf fp32 Q; n0==128 -> Ch/Cl K; n0==256 -> Cv V hi
__global__ __launch_bounds__(256) void hmma_gemm_pre(
    const __nv_bfloat16* __restrict__ Ah, const __nv_bfloat16* __restrict__ Al,
    const __nv_bfloat16* __restrict__ Bh, const __nv_bfloat16* __restrict__ Bl,
    const float* __restrict__ bias, int N, int mode,
    float* __restrict__ Cf,
    __nv_bfloat16* __restrict__ Ch, __nv_bfloat16* __restrict__ Cl,
    __nv_bfloat16* __restrict__ Cv)
{
    __shared__ __align__(16) uint8_t sAh[32 * 128];
    __shared__ __align__(16) uint8_t sAl[32 * 128];
    __shared__ __align__(16) uint8_t sBh[2][64 * 128];
    __shared__ __align__(16) uint8_t sBl[2][64 * 128];

    const int tid  = threadIdx.x;
    const int lane = tid & 31;
    const int w    = tid >> 5;
    const int wm   = w & 1;
    const int wn   = w >> 1;
    const int m0   = blockIdx.y * 32;
    const int n0   = blockIdx.x * 128;

    const int rq = lane >> 2;
    const int d0 = (lane & 3) * 2;
    const int lr16  = lane & 15;
    const int lclog = lane >> 4;
    const int lm = lane >> 3, lr = lane & 7;

    float c[4][4];
    #pragma unroll
    for (int i = 0; i < 4; i++)
        #pragma unroll
        for (int j = 0; j < 4; j++) c[i][j] = 0.f;

    const uint32_t aAh = smem_u32(sAh);
    const uint32_t aAl = smem_u32(sAl);
    const uint32_t aBh = smem_u32(sBh[wn >> 1]);
    const uint32_t aBl = smem_u32(sBl[wn >> 1]);

    #pragma unroll
    for (int khalf = 0; khalf < 2; ++khalf) {
        __syncthreads();
        // ---- stage A: 32 rows x 64 k (1 uint4 per plane per thread) --------
        {
            int row = tid >> 3, chunk = tid & 7;
            uint32_t off = (uint32_t)(row * 128) + (((uint32_t)(chunk ^ (row & 7))) << 4);
            const uint4* sh = (const uint4*)(Ah + (size_t)(m0 + row) * 128 + khalf * 64);
            const uint4* sl = (const uint4*)(Al + (size_t)(m0 + row) * 128 + khalf * 64);
            *(uint4*)(sAh + off) = sh[chunk];
            *(uint4*)(sAl + off) = sl[chunk];
        }
        // ---- stage B: 2 n-halves x 64 k x 64 n ------------------------------
        #pragma unroll
        for (int rep = 0; rep < 4; ++rep) {
            int idx = rep * 256 + tid;
            int nh = idx >> 9, kr = (idx >> 3) & 63, chunk = idx & 7;
            uint32_t off = (uint32_t)(kr * 128) + (((uint32_t)(chunk ^ (kr & 7))) << 4);
            const uint4* sh = (const uint4*)(Bh + (size_t)(khalf * 64 + kr) * N + n0 + nh * 64);
            const uint4* sl = (const uint4*)(Bl + (size_t)(khalf * 64 + kr) * N + n0 + nh * 64);
            *(uint4*)(sBh[nh] + off) = sh[chunk];
            *(uint4*)(sBl[nh] + off) = sl[chunk];
        }
        __syncthreads();

        #pragma unroll
        for (int s = 0; s < 4; ++s) {
            uint32_t ah[4], al[4];
            {
                int row = wm * 16 + lr16;
                uint32_t off = (uint32_t)(row * 128) + ((((uint32_t)(s * 2 + lclog) ^ (row & 7)) << 4));
                ldm_x4(ah, aAh + off);
                ldm_x4(al, aAl + off);
            }
            int rowB = s * 16 + ((lm & 1) << 3) + lr;
            uint32_t rbase = (uint32_t)(rowB * 128);
            #pragma unroll
            for (int g = 0; g < 2; ++g) {
                uint32_t chunk = (uint32_t)(((wn & 1) * 2 + g) * 2 + (lm >> 1));
                uint32_t off = rbase + ((chunk ^ (rowB & 7)) << 4);
                uint32_t bh[4], bl[4];
                ldm_x4_t(bh, aBh + off);
                ldm_x4_t(bl, aBl + off);
                mma_bf16(c[g*2],   ah, bh[0], bh[1]);
                mma_bf16(c[g*2],   ah, bl[0], bl[1]);
                mma_bf16(c[g*2],   al, bh[0], bh[1]);
                mma_bf16(c[g*2+1], ah, bh[2], bh[3]);
                mma_bf16(c[g*2+1], ah, bl[2], bl[3]);
                mma_bf16(c[g*2+1], al, bh[2], bh[3]);
            }
        }
    }

    const int rowA = m0 + wm * 16 + rq;
    #pragma unroll
    for (int t8 = 0; t8 < 4; ++t8) {
        int col = n0 + wn * 32 + t8 * 8 + d0;
        float b0 = bias[col], b1 = bias[col + 1];
        float v00 = c[t8][0] + b0, v01 = c[t8][1] + b1;
        float v10 = c[t8][2] + b0, v11 = c[t8][3] + b1;

        if (mode == 1) {
            v00 = fmaxf(v00, 0.f); v01 = fmaxf(v01, 0.f);
            v10 = fmaxf(v10, 0.f); v11 = fmaxf(v11, 0.f);
            float h00 = bfr(v00), h01 = bfr(v01), h10 = bfr(v10), h11 = bfr(v11);
            ((uint32_t*)Ch)[((size_t)rowA * 128 + col) >> 1]       = pack_bf16x2(h00, h01);
            ((uint32_t*)Cl)[((size_t)rowA * 128 + col) >> 1]       = pack_bf16x2(v00 - h00, v01 - h01);
            ((uint32_t*)Ch)[((size_t)(rowA + 8) * 128 + col) >> 1] = pack_bf16x2(h10, h11);
            ((uint32_t*)Cl)[((size_t)(rowA + 8) * 128 + col) >> 1] = pack_bf16x2(v10 - h10, v11 - h11);
        } else {
            if (n0 == 0) {
                *(float2*)(Cf + (size_t)rowA * 128 + col)       = make_float2(v00, v01);
                *(float2*)(Cf + (size_t)(rowA + 8) * 128 + col) = make_float2(v10, v11);
            } else if (n0 == 128) {
                int kc = col - 128;
                float h00 = bfr(v00), h01 = bfr(v01), h10 = bfr(v10), h11 = bfr(v11);
                ((uint32_t*)Ch)[((size_t)rowA * 128 + kc) >> 1]       = pack_bf16x2(h00, h01);
                ((uint32_t*)Cl)[((size_t)rowA * 128 + kc) >> 1]       = pack_bf16x2(v00 - h00, v01 - h01);
                ((uint32_t*)Ch)[((size_t)(rowA + 8) * 128 + kc) >> 1] = pack_bf16x2(h10, h11);
                ((uint32_t*)Cl)[((size_t)(rowA + 8) * 128 + kc) >> 1] = pack_bf16x2(v10 - h10, v11 - h11);
            } else {
                int vc = col - 256;
                ((uint32_t*)Cv)[((size_t)rowA * 128 + vc) >> 1]       = pack_bf16x2(bfr(v00), bfr(v01));
                ((uint32_t*)Cv)[((size_t)(rowA + 8) * 128 + vc) >> 1] = pack_bf16x2(bfr(v10), bfr(v11));
            }
        }
    }
}

// ============ fused ff2 GEMM + residual add + LayerNorm (BM=32, N=128) =====
#define SA_H 0
#define SA_L 4096
#define SB_H 8192
#define SB_L 24576
__global__ __launch_bounds__(256) void hmma_gemm_ln(
    const __nv_bfloat16* __restrict__ Ah, const __nv_bfloat16* __restrict__ Al,
    const __nv_bfloat16* __restrict__ Bh, const __nv_bfloat16* __restrict__ Bl,
    const float* __restrict__ bias, const float* __restrict__ xin,
    const float* __restrict__ gamma, const float* __restrict__ beta,
    float* __restrict__ out)
{
    __shared__ __align__(16) uint8_t sbuf[40960];

    const int tid  = threadIdx.x;
    const int lane = tid & 31;
    const int w    = tid >> 5;
    const int wm   = w & 1;
    const int wn   = w >> 1;
    const int m0   = blockIdx.y * 32;

    const int rq = lane >> 2;
    const int d0 = (lane & 3) * 2;
    const int lr16  = lane & 15;
    const int lclog = lane >> 4;
    const int lm = lane >> 3, lr = lane & 7;

    float c[4][4];
    #pragma unroll
    for (int i = 0; i < 4; i++)
        #pragma unroll
        for (int j = 0; j < 4; j++) c[i][j] = 0.f;

    const uint32_t aAh = smem_u32(sbuf + SA_H);
    const uint32_t aAl = smem_u32(sbuf + SA_L);
    const uint32_t aBh = smem_u32(sbuf + SB_H + (wn >> 1) * 8192);
    const uint32_t aBl = smem_u32(sbuf + SB_L + (wn >> 1) * 8192);

    #pragma unroll
    for (int khalf = 0; khalf < 2; ++khalf) {
        __syncthreads();
        {
            int row = tid >> 3, chunk = tid & 7;
            uint32_t off = (uint32_t)(row * 128) + (((uint32_t)(chunk ^ (row & 7))) << 4);
            const uint4* sh = (const uint4*)(Ah + (size_t)(m0 + row) * 128 + khalf * 64);
            const uint4* sl = (const uint4*)(Al + (size_t)(m0 + row) * 128 + khalf * 64);
            *(uint4*)(sbuf + SA_H + off) = sh[chunk];
            *(uint4*)(sbuf + SA_L + off) = sl[chunk];
        }
        #pragma unroll
        for (int rep = 0; rep < 4; ++rep) {
            int idx = rep * 256 + tid;
            int nh = idx >> 9, kr = (idx >> 3) & 63, chunk = idx & 7;
            uint32_t off = (uint32_t)(kr * 128) + (((uint32_t)(chunk ^ (kr & 7))) << 4);
            const uint4* sh = (const uint4*)(Bh + (size_t)(khalf * 64 + kr) * 128 + nh * 64);
            const uint4* sl = (const uint4*)(Bl + (size_t)(khalf * 64 + kr) * 128 + nh * 64);
            *(uint4*)(sbuf + SB_H + nh * 8192 + off) = sh[chunk];
            *(uint4*)(sbuf + SB_L + nh * 8192 + off) = sl[chunk];
        }
        __syncthreads();

        #pragma unroll
        for (int s = 0; s < 4; ++s) {
            uint32_t ah[4], al[4];
            {
                int row = wm * 16 + lr16;
                uint32_t off = (uint32_t)(row * 128) + ((((uint32_t)(s * 2 + lclog) ^ (row & 7)) << 4));
                ldm_x4(ah, aAh + off);
                ldm_x4(al, aAl + off);
            }
            int rowB = s * 16 + ((lm & 1) << 3) + lr;
            uint32_t rbase = (uint32_t)(rowB * 128);
            #pragma unroll
            for (int g = 0; g < 2; ++g) {
                uint32_t chunk = (uint32_t)(((wn & 1) * 2 + g) * 2 + (lm >> 1));
                uint32_t off = rbase + ((chunk ^ (rowB & 7)) << 4);
                uint32_t bh[4], bl[4];
                ldm_x4_t(bh, aBh + off);
                ldm_x4_t(bl, aBl + off);
                mma_bf16(c[g*2],   ah, bh[0], bh[1]);
                mma_bf16(c[g*2],   ah, bl[0], bl[1]);
                mma_bf16(c[g*2],   al, bh[0], bh[1]);
                mma_bf16(c[g*2+1], ah, bh[2], bh[3]);
                mma_bf16(c[g*2+1], ah, bl[2], bl[3]);
                mma_bf16(c[g*2+1], al, bh[2], bh[3]);
            }
        }
    }

    // ---- GEMM results (+bias) -> smem sC (overlays staging) ----------------
    __syncthreads();
    float* sC = (float*)sbuf;                 // 32 x 128 fp32 = 16 KB
    {
        const int rowT = wm * 16 + rq;
        #pragma unroll
        for (int t8 = 0; t8 < 4; ++t8) {
            int col = wn * 32 + t8 * 8 + d0;
            float b0 = bias[col], b1 = bias[col + 1];
            sC[rowT * 128 + col]           = c[t8][0] + b0;
            sC[rowT * 128 + col + 1]       = c[t8][1] + b1;
            sC[(rowT + 8) * 128 + col]     = c[t8][2] + b0;
            sC[(rowT + 8) * 128 + col + 1] = c[t8][3] + b1;
        }
    }
    __syncthreads();

    // ---- LayerNorm: 8 threads per row, 16 cols each -------------------------
    {
        const int row = tid >> 3;
        const int q8 = tid & 7;
        float* vr = sC + row * 128 + q8 * 16;
        const float* xr = xin + (size_t)(m0 + row) * 128 + q8 * 16;

        float s = 0.f;
        #pragma unroll
        for (int j = 0; j < 16; j++) {
            float v = vr[j] + xr[j];
            vr[j] = v;
            s += v;
        }
        s += __shfl_xor_sync(0xffffffffu, s, 1);
        s += __shfl_xor_sync(0xffffffffu, s, 2);
        s += __shfl_xor_sync(0xffffffffu, s, 4);
        float mu = s * (1.f / 128.f);

        float q = 0.f;
        #pragma unroll
        for (int j = 0; j < 16; j++) {
            float d = vr[j] - mu;
            q += d * d;
        }
        q += __shfl_xor_sync(0xffffffffu, q, 1);
        q += __shfl_xor_sync(0xffffffffu, q, 2);
        q += __shfl_xor_sync(0xffffffffu, q, 4);
        float rs = rsqrtf(q * (1.f / 128.f) + LN_EPS);

        float* orow = out + (size_t)(m0 + row) * 128 + q8 * 16;
        #pragma unroll
        for (int j = 0; j < 16; j++) {
            orow[j] = (vr[j] - mu) * rs * gamma[q8 * 16 + j] + beta[q8 * 16 + j];
        }
    }
}

// ================= HMMA flash attention (cp.async double-buffered) =========
#define KROWB 48
#define CHUNKB (128 * KROWB)          // 6144 per plane
#define BUFB   (3 * CHUNKB)           // 18432 per buffer

__device__ __forceinline__ void attn_stage(uint32_t sbase, int buf, int c0,
                                           int b, int h, int tid) {
    const uint32_t dbase = sbase + (uint32_t)buf * BUFB;
    if (tid < 128) {
        const __nv_bfloat16* kh = g_kh + (size_t)(b * L_ + c0 + tid) * D_ + h * HD_;
        const __nv_bfloat16* kl = g_kl + (size_t)(b * L_ + c0 + tid) * D_ + h * HD_;
        uint32_t dk = dbase + (uint32_t)(tid * KROWB);
        cp16(dk,                kh);
        cp16(dk + 16,           kh + 8);
        cp16(dk + CHUNKB,       kl);
        cp16(dk + CHUNKB + 16,  kl + 8);
    } else {
        const int r = tid - 128;
        const __nv_bfloat16* vh = g_vh + (size_t)(b * L_ + c0 + r) * D_ + h * HD_;
        uint32_t dv = dbase + 2 * CHUNKB + (uint32_t)(r * KROWB);
        cp16(dv,      vh);
        cp16(dv + 16, vh + 8);
    }
}

__global__ __launch_bounds__(256) void attn_mma_kernel(
    float* __restrict__ po0, float* __restrict__ po1, float* __restrict__ pl)
{
    __shared__ __align__(16) uint8_t sKV[2 * BUFB];   // 36 KB

    const int tid  = threadIdx.x;
    const int lane = tid & 31;
    const int w    = tid >> 5;         // 0..7, warp owns q rows w*16..+15
    const int b    = blockIdx.y >> 3;
    const int h    = blockIdx.y & 7;
    const int q0   = blockIdx.x << 7;
    const int zz   = blockIdx.z;

    const int rq = lane >> 2;
    const int d0 = (lane & 3) * 2;

    const float qscale = 0.25f * 1.44269504088896f;
    const uint32_t sbase = smem_u32(sKV);

    // ---- Q fragment (hi/lo bf16 split) --------------------------------------
    uint32_t ah[4], al[4];
    {
        int rowA = q0 + w * 16 + rq;
        const float* qb = g_q + (size_t)(b * L_ + rowA) * D_ + h * HD_;
        float2 e0 = *(const float2*)(qb + d0);
        float2 e1 = *(const float2*)(qb + (size_t)8 * D_ + d0);
        float2 e2 = *(const float2*)(qb + d0 + 8);
        float2 e3 = *(const float2*)(qb + (size_t)8 * D_ + d0 + 8);
        float v[8] = {e0.x * qscale, e0.y * qscale, e1.x * qscale, e1.y * qscale,
                      e2.x * qscale, e2.y * qscale, e3.x * qscale, e3.y * qscale};
        #pragma unroll
        for (int j = 0; j < 4; j++) {
            float hx = bfr(v[2*j]), hy = bfr(v[2*j+1]);
            ah[j] = pack_bf16x2(hx, hy);
            al[j] = pack_bf16x2(v[2*j] - hx, v[2*j+1] - hy);
        }
    }

    const uint4* mbase = (const uint4*)g_maskbits;
    const int mrowA = (b * L_ + q0 + w * 16 + rq) * 8;
    const int mrowB = mrowA + 8 * 8;

    const int lm = lane >> 3, lr = lane & 7;
    const uint32_t kOff = (uint32_t)((((lm >> 1) << 3) + lr) * KROWB + ((lm & 1) << 4));
    const uint32_t vOff = (uint32_t)((((lm & 1) << 3) + lr) * KROWB + ((lm >> 1) << 4));

    float o[2][4];
    float lac[4];
    #pragma unroll
    for (int n = 0; n < 2; n++)
        #pragma unroll
        for (int i = 0; i < 4; i++) o[n][i] = 0.f;
    #pragma unroll
    for (int i = 0; i < 4; i++) lac[i] = 0.f;

    const int ck0 = zz * 4;
    // prologue: stage first chunk
    attn_stage(sbase, ck0 & 1, ck0 << 7, b, h, tid);
    CP_COMMIT();

    for (int ck = ck0; ck < ck0 + 4; ++ck) {
        const int c0 = ck << 7;
        const int buf = ck & 1;

        if (ck < ck0 + 3) {
            attn_stage(sbase, (ck + 1) & 1, (ck + 1) << 7, b, h, tid);
            CP_COMMIT();
            asm volatile("cp.async.wait_group 1;" ::: "memory");
        } else {
            asm volatile("cp.async.wait_group 0;" ::: "memory");
        }
        __syncthreads();

        const uint32_t aKh = sbase + (uint32_t)buf * BUFB + kOff;
        const uint32_t aKl = aKh + CHUNKB;
        const uint32_t aVh = sbase + (uint32_t)buf * BUFB + 2 * CHUNKB + vOff;

        uint32_t mwa[4], mwb[4];
        {
            uint4 a = mbase[mrowA + (c0 >> 7)];
            uint4 bq = mbase[mrowB + (c0 >> 7)];
            mwa[0] = a.x;  mwa[1] = a.y;  mwa[2] = a.z;  mwa[3] = a.w;
            mwb[0] = bq.x; mwb[1] = bq.y; mwb[2] = bq.z; mwb[3] = bq.w;
        }

        #pragma unroll
        for (int s = 0; s < 8; ++s) {
            const uint32_t so = (uint32_t)(s * 16 * KROWB);
            uint32_t kh[4], kl[4], vh[4];
            ldm_x4(kh, aKh + so);
            ldm_x4(kl, aKl + so);
            ldm_x4_t(vh, aVh + so);
            const int sh = ((s & 1) << 4) + d0;

            float cA0[4] = {0.f, 0.f, 0.f, 0.f};
            float cB0[4] = {0.f, 0.f, 0.f, 0.f};
            float cA1[4] = {0.f, 0.f, 0.f, 0.f};
            float cB1[4] = {0.f, 0.f, 0.f, 0.f};
            mma_bf16(cA0, ah, kh[0], kh[1]);
            mma_bf16(cB0, ah, kl[0], kl[1]);
            mma_bf16(cA1, ah, kh[2], kh[3]);
            mma_bf16(cB1, ah, kl[2], kl[3]);
            mma_bf16(cB0, al, kh[0], kh[1]);
            mma_bf16(cB1, al, kh[2], kh[3]);

            uint32_t wa = mwa[s >> 1] >> sh;
            uint32_t wb = mwb[s >> 1] >> sh;

            float p00 = (wa & 1u)     ? 0.f : ex2f(cA0[0] + cB0[0]);
            float p01 = (wa & 2u)     ? 0.f : ex2f(cA0[1] + cB0[1]);
            float p02 = (wb & 1u)     ? 0.f : ex2f(cA0[2] + cB0[2]);
            float p03 = (wb & 2u)     ? 0.f : ex2f(cA0[3] + cB0[3]);
            float p10 = (wa & 0x100u) ? 0.f : ex2f(cA1[0] + cB1[0]);
            float p11 = (wa & 0x200u) ? 0.f : ex2f(cA1[1] + cB1[1]);
            float p12 = (wb & 0x100u) ? 0.f : ex2f(cA1[2] + cB1[2]);
            float p13 = (wb & 0x200u) ? 0.f : ex2f(cA1[3] + cB1[3]);

            uint32_t ap[4];
            ap[0] = pack_bf16x2(p00, p01);
            ap[1] = pack_bf16x2(p02, p03);
            ap[2] = pack_bf16x2(p10, p11);
            ap[3] = pack_bf16x2(p12, p13);

            mma_bf16(o[0], ap, vh[0], vh[1]);
            mma_bf16(o[1], ap, vh[2], vh[3]);
            mma_bf16(lac, ap, ONES2, ONES2);
        }
        __syncthreads();
    }

    // ---- epilogue: write partial O and l ------------------------------------
    float* po = zz ? po1 : po0;
    {
        int rowA = q0 + w * 16 + rq;
        float* oA = po + (size_t)(b * L_ + rowA) * D_ + h * HD_;
        float* oB = oA + (size_t)8 * D_;
        #pragma unroll
        for (int n = 0; n < 2; n++) {
            *(float2*)(oA + n * 8 + d0) = make_float2(o[n][0], o[n][1]);
            *(float2*)(oB + n * 8 + d0) = make_float2(o[n][2], o[n][3]);
        }
        if ((lane & 3) == 0) {
            pl[(size_t)zz * ROWS * H_ + (size_t)(b * L_ + rowA) * H_ + h]     = lac[0];
            pl[(size_t)zz * ROWS * H_ + (size_t)(b * L_ + rowA + 8) * H_ + h] = lac[2];
        }
    }
}

// ---------------- combine partials + residual add + LayerNorm --------------
__global__ __launch_bounds__(128) void combine_add_ln_kernel(
    const float* __restrict__ xin,
    const float* __restrict__ po0, const float* __restrict__ po1,
    const float* __restrict__ pl,
    const float* __restrict__ gamma, const float* __restrict__ beta,
    float* __restrict__ out,
    __nv_bfloat16* __restrict__ oh, __nv_bfloat16* __restrict__ ol)
{
    const int row = blockIdx.x;
    const int t = threadIdx.x;
    const int head = t >> 4;
    const int warp = t >> 5, lane = t & 31;
    __shared__ float red1[4], red2[4];

    float l = pl[(size_t)row * H_ + head] + pl[(size_t)ROWS * H_ + (size_t)row * H_ + head];
    float osum = po0[(size_t)row * D_ + t] + po1[(size_t)row * D_ + t];
    float v = xin[(size_t)row * D_ + t] + ((l > 0.f) ? (osum / l) : 0.f);

    float s = v;
    #pragma unroll
    for (int o = 16; o; o >>= 1) s += __shfl_xor_sync(0xffffffffu, s, o);
    if (lane == 0) red1[warp] = s;
    __syncthreads();
    float mu = (red1[0] + red1[1] + red1[2] + red1[3]) * (1.f / D_);

    float c = v - mu;
    float q = c * c;
    #pragma unroll
    for (int o = 16; o; o >>= 1) q += __shfl_xor_sync(0xffffffffu, q, o);
    if (lane == 0) red2[warp] = q;
    __syncthreads();
    float var = (red2[0] + red2[1] + red2[2] + red2[3]) * (1.f / D_);

    float y = c * rsqrtf(var + LN_EPS) * gamma[t] + beta[t];
    out[(size_t)row * D_ + t] = y;
    float hy = bfr(y);
    oh[(size_t)row * D_ + t] = __float2bfloat16_rn(hy);
    ol[(size_t)row * D_ + t] = __float2bfloat16_rn(y - hy);
}

// ---------------- launch --------------------------------------------------
extern "C" void kernel_launch(void* const* d_in, const int* in_sizes, int n_in,
                              void* d_out, int out_size)
{
    const float* edge_x    = (const float*)d_in[0];
    const void*  edge_mask = d_in[1];
    const float* in_proj_w = (const float*)d_in[2];
    const float* in_proj_b = (const float*)d_in[3];
    const float* w1        = (const float*)d_in[4];
    const float* b1        = (const float*)d_in[5];
    const float* w2        = (const float*)d_in[6];
    const float* b2        = (const float*)d_in[7];
    const float* g1        = (const float*)d_in[8];
    const float* beta1     = (const float*)d_in[9];
    const float* g2        = (const float*)d_in[10];
    const float* beta2     = (const float*)d_in[11];
    float* out = (float*)d_out;

    void *p_q, *p_kh, *p_kl, *p_vh, *p_xh, *p_xl;
    void *p_wqh, *p_wql, *p_w1h, *p_w1l, *p_w2h, *p_w2l;
    void *p_f1h, *p_f1l, *p_x1h, *p_x1l;
    void *p_po0, *p_po1, *p_pl, *p_x1;
    cudaGetSymbolAddress(&p_q,   g_q);
    cudaGetSymbolAddress(&p_kh,  g_kh);
    cudaGetSymbolAddress(&p_kl,  g_kl);
    cudaGetSymbolAddress(&p_vh,  g_vh);
    cudaGetSymbolAddress(&p_xh,  g_xh);
    cudaGetSymbolAddress(&p_xl,  g_xl);
    cudaGetSymbolAddress(&p_wqh, g_wqh);
    cudaGetSymbolAddress(&p_wql, g_wql);
    cudaGetSymbolAddress(&p_w1h, g_w1h);
    cudaGetSymbolAddress(&p_w1l, g_w1l);
    cudaGetSymbolAddress(&p_w2h, g_w2h);
    cudaGetSymbolAddress(&p_w2l, g_w2l);
    cudaGetSymbolAddress(&p_f1h, g_f1h);
    cudaGetSymbolAddress(&p_f1l, g_f1l);
    cudaGetSymbolAddress(&p_x1h, g_x1h);
    cudaGetSymbolAddress(&p_x1l, g_x1l);
    cudaGetSymbolAddress(&p_po0, g_po0);
    cudaGetSymbolAddress(&p_po1, g_po1);
    cudaGetSymbolAddress(&p_pl,  g_pl);
    cudaGetSymbolAddress(&p_x1,  g_x1);

    // 1) mask detect + bitpack
    detect_mask_kernel<<<1, 32>>>((const unsigned char*)edge_mask);
    maskbits_kernel<<<NMASKW / 256, 256>>>(edge_mask);

    // 2) pre-convert: edge_x + all weights (one launch for weights)
    conv_kernel<<<ROWS * D_ / 256, 256>>>(edge_x, (__nv_bfloat16*)p_xh, (__nv_bfloat16*)p_xl, ROWS * D_);
    conv_weights_kernel<<<320, 256>>>(in_proj_w, w1, w2);

    // 3) QKV projection (mode 2): Q fp32, K hi/lo, V hi
    {
        dim3 grid(3, ROWS / 32);
        hmma_gemm_pre<<<grid, 256>>>((const __nv_bfloat16*)p_xh, (const __nv_bfloat16*)p_xl,
                                     (const __nv_bfloat16*)p_wqh, (const __nv_bfloat16*)p_wql,
                                     in_proj_b, 3 * D_, 2,
                                     (float*)p_q, (__nv_bfloat16*)p_kh, (__nv_bfloat16*)p_kl,
                                     (__nv_bfloat16*)p_vh);
    }

    // 4) masked attention -> partial O, l (cp.async double-buffered)
    {
        dim3 grid(L_ / 128, B_ * H_, 2);
        attn_mma_kernel<<<grid, 256>>>((float*)p_po0, (float*)p_po1, (float*)p_pl);
    }

    // 5) x1 = LN(edge_x + combine(O,l)), emit fp32 + hi/lo planes
    combine_add_ln_kernel<<<ROWS, 128>>>(edge_x, (const float*)p_po0,
                                         (const float*)p_po1, (const float*)p_pl,
                                         g1, beta1, (float*)p_x1,
                                         (__nv_bfloat16*)p_x1h, (__nv_bfloat16*)p_x1l);

    // 6) ff1 = relu(x1 @ w1 + b1) -> hi/lo planes (mode 1)
    {
        dim3 grid(1, ROWS / 32);
        hmma_gemm_pre<<<grid, 256>>>((const __nv_bfloat16*)p_x1h, (const __nv_bfloat16*)p_x1l,
                                     (const __nv_bfloat16*)p_w1h, (const __nv_bfloat16*)p_w1l,
                                     b1, D_, 1,
                                     nullptr, (__nv_bfloat16*)p_f1h, (__nv_bfloat16*)p_f1l, nullptr);
    }
    // 7) out = LN(x1 + ff1 @ w2 + b2)  (fused GEMM + LN, BM=32)
    {
        dim3 grid(1, ROWS / 32);
        hmma_gemm_ln<<<grid, 256>>>((const __nv_bfloat16*)p_f1h, (const __nv_bfloat16*)p_f1l,
                                    (const __nv_bfloat16*)p_w2h, (const __nv_bfloat16*)p_w2l,
                                    b2, (const float*)p_x1, g2, beta2, out);
    }
}

// round 9
// speedup vs baseline: 1.0411x; 1.0133x over previous
#include <cuda_runtime.h>
#include <cuda_bf16.h>
#include <math_constants.h>
#include <cstdint>

// Problem constants
#define B_   16
#define L_   1024
#define D_   128
#define H_   8
#define HD_  16
#define ROWS (B_ * L_)          // 16384
#define LN_EPS 1e-5f
#define NMASKW (B_ * L_ * L_ / 32)

// ---------------- scratch (device globals) ---------------------------------
__device__ float g_q  [ROWS * D_];                 // Q fp32, PRE-SCALED
__device__ __nv_bfloat16 g_kh[ROWS * D_];
__device__ __nv_bfloat16 g_kl[ROWS * D_];
__device__ __nv_bfloat16 g_vh[ROWS * D_];
__device__ __nv_bfloat16 g_xh[ROWS * D_];
__device__ __nv_bfloat16 g_xl[ROWS * D_];
__device__ __nv_bfloat16 g_wqh[D_ * 3 * D_];
__device__ __nv_bfloat16 g_wql[D_ * 3 * D_];
__device__ __nv_bfloat16 g_w1h[D_ * D_];
__device__ __nv_bfloat16 g_w1l[D_ * D_];
__device__ __nv_bfloat16 g_w2h[D_ * D_];
__device__ __nv_bfloat16 g_w2l[D_ * D_];
__device__ __nv_bfloat16 g_f1h[ROWS * D_];
__device__ __nv_bfloat16 g_f1l[ROWS * D_];
__device__ __nv_bfloat16 g_x1h[ROWS * D_];
__device__ __nv_bfloat16 g_x1l[ROWS * D_];
__device__ float g_ctx[ROWS * D_];                 // normalized attention out
__device__ float g_x1 [ROWS * D_];
__device__ uint32_t g_maskbits[NMASKW];
__device__ int g_mask_is_i32;

// ============================ helpers ======================================
__device__ __forceinline__ uint32_t smem_u32(const void* p) {
    uint32_t a;
    asm("{ .reg .u64 t; cvta.to.shared.u64 t, %1; cvt.u32.u64 %0, t; }"
        : "=r"(a) : "l"(p));
    return a;
}
__device__ __forceinline__ uint32_t pack_bf16x2(float e, float o) {
    uint32_t r;
    asm("cvt.rn.bf16x2.f32 %0, %1, %2;" : "=r"(r) : "f"(o), "f"(e));
    return r;
}
__device__ __forceinline__ float ex2f(float x) {
    float y; asm("ex2.approx.f32 %0, %1;" : "=f"(y) : "f"(x)); return y;
}
__device__ __forceinline__ float bfr(float x) {
    return __bfloat162float(__float2bfloat16_rn(x));
}
__device__ __forceinline__ void mma_bf16(float* c, const uint32_t* a, uint32_t b0, uint32_t b1) {
    asm volatile("mma.sync.aligned.m16n8k16.row.col.f32.bf16.bf16.f32 "
        "{%0,%1,%2,%3}, {%4,%5,%6,%7}, {%8,%9}, {%0,%1,%2,%3};"
        : "+f"(c[0]), "+f"(c[1]), "+f"(c[2]), "+f"(c[3])
        : "r"(a[0]), "r"(a[1]), "r"(a[2]), "r"(a[3]), "r"(b0), "r"(b1));
}
__device__ __forceinline__ void ldm_x4(uint32_t* r, uint32_t addr) {
    asm volatile("ldmatrix.sync.aligned.m8n8.x4.shared.b16 {%0,%1,%2,%3}, [%4];"
        : "=r"(r[0]), "=r"(r[1]), "=r"(r[2]), "=r"(r[3]) : "r"(addr));
}
__device__ __forceinline__ void ldm_x4_t(uint32_t* r, uint32_t addr) {
    asm volatile("ldmatrix.sync.aligned.m8n8.x4.trans.shared.b16 {%0,%1,%2,%3}, [%4];"
        : "=r"(r[0]), "=r"(r[1]), "=r"(r[2]), "=r"(r[3]) : "r"(addr));
}
__device__ __forceinline__ void cp16(uint32_t dst, const void* src) {
    asm volatile("cp.async.cg.shared.global [%0], [%1], 16;"
        :: "r"(dst), "l"(src) : "memory");
}
#define CP_COMMIT() asm volatile("cp.async.commit_group;" ::: "memory")
#define ONES2 0x3F803F80u

// ---------------- mask detect + bitpack + conversions ----------------------
__global__ void detect_mask_kernel(const unsigned char* __restrict__ m) {
    if (threadIdx.x == 0 && blockIdx.x == 0) {
        int i32like = 1;
        for (int i = 0; i < 4096; i += 4) {
            unsigned char b0 = m[i], b1 = m[i+1], b2 = m[i+2], b3 = m[i+3];
            if ((b1 | b2 | b3) != 0 || b0 > 1) { i32like = 0; break; }
        }
        g_mask_is_i32 = i32like;
    }
}
__global__ void maskbits_kernel(const void* __restrict__ in) {
    int wIdx = blockIdx.x * blockDim.x + threadIdx.x;
    if (wIdx >= NMASKW) return;
    uint32_t bits = 0;
    if (g_mask_is_i32) {
        const int* p = (const int*)in + (size_t)wIdx * 32;
        #pragma unroll
        for (int j = 0; j < 32; j++) bits |= (p[j] != 0 ? 1u : 0u) << j;
    } else {
        const uint4* p = (const uint4*)((const uint8_t*)in + (size_t)wIdx * 32);
        uint4 a = p[0], bq = p[1];
        uint32_t ww[8] = {a.x, a.y, a.z, a.w, bq.x, bq.y, bq.z, bq.w};
        #pragma unroll
        for (int u = 0; u < 8; u++)
            #pragma unroll
            for (int j = 0; j < 4; j++)
                bits |= (((ww[u] >> (8 * j)) & 0xFFu) ? 1u : 0u) << (u * 4 + j);
    }
    g_maskbits[wIdx] = bits;
}
__global__ void conv_kernel(const float* __restrict__ src,
                            __nv_bfloat16* __restrict__ dh,
                            __nv_bfloat16* __restrict__ dl, int n) {
    int i = blockIdx.x * blockDim.x + threadIdx.x;
    if (i >= n) return;
    float f = src[i];
    float h = bfr(f);
    dh[i] = __float2bfloat16_rn(h);
    dl[i] = __float2bfloat16_rn(f - h);
}
__global__ void conv_weights_kernel(const float* __restrict__ wq,
                                    const float* __restrict__ w1,
                                    const float* __restrict__ w2) {
    int i = blockIdx.x * blockDim.x + threadIdx.x;
    const float* src; __nv_bfloat16 *dh, *dl; int j;
    if (i < 49152)      { src = wq; dh = g_wqh; dl = g_wql; j = i; }
    else if (i < 65536) { src = w1; dh = g_w1h; dl = g_w1l; j = i - 49152; }
    else                { src = w2; dh = g_w2h; dl = g_w2l; j = i - 65536; }
    float f = src[j];
    float h = bfr(f);
    dh[j] = __float2bfloat16_rn(h);
    dl[j] = __float2bfloat16_rn(f - h);
}

// ================= HMMA GEMM BM=32 (pre-converted bf16 planes) =============
// mode 1: relu(A@B + bias) -> Ch/Cl planes (N=128)
// mode 2: QKV: n0==0 -> Cf fp32 Q (PRE-SCALED); n0==128 -> Ch/Cl K; n0==256 -> Cv V hi
__global__ __launch_bounds__(256) void hmma_gemm_pre(
    const __nv_bfloat16* __restrict__ Ah, const __nv_bfloat16* __restrict__ Al,
    const __nv_bfloat16* __restrict__ Bh, const __nv_bfloat16* __restrict__ Bl,
    const float* __restrict__ bias, int N, int mode,
    float* __restrict__ Cf,
    __nv_bfloat16* __restrict__ Ch, __nv_bfloat16* __restrict__ Cl,
    __nv_bfloat16* __restrict__ Cv)
{
    __shared__ __align__(16) uint8_t sAh[32 * 128];
    __shared__ __align__(16) uint8_t sAl[32 * 128];
    __shared__ __align__(16) uint8_t sBh[2][64 * 128];
    __shared__ __align__(16) uint8_t sBl[2][64 * 128];

    const int tid  = threadIdx.x;
    const int lane = tid & 31;
    const int w    = tid >> 5;
    const int wm   = w & 1;
    const int wn   = w >> 1;
    const int m0   = blockIdx.y * 32;
    const int n0   = blockIdx.x * 128;

    const int rq = lane >> 2;
    const int d0 = (lane & 3) * 2;
    const int lr16  = lane & 15;
    const int lclog = lane >> 4;
    const int lm = lane >> 3, lr = lane & 7;

    float c[4][4];
    #pragma unroll
    for (int i = 0; i < 4; i++)
        #pragma unroll
        for (int j = 0; j < 4; j++) c[i][j] = 0.f;

    const uint32_t aAh = smem_u32(sAh);
    const uint32_t aAl = smem_u32(sAl);
    const uint32_t aBh = smem_u32(sBh[wn >> 1]);
    const uint32_t aBl = smem_u32(sBl[wn >> 1]);

    #pragma unroll
    for (int khalf = 0; khalf < 2; ++khalf) {
        __syncthreads();
        {
            int row = tid >> 3, chunk = tid & 7;
            uint32_t off = (uint32_t)(row * 128) + (((uint32_t)(chunk ^ (row & 7))) << 4);
            const uint4* sh = (const uint4*)(Ah + (size_t)(m0 + row) * 128 + khalf * 64);
            const uint4* sl = (const uint4*)(Al + (size_t)(m0 + row) * 128 + khalf * 64);
            *(uint4*)(sAh + off) = sh[chunk];
            *(uint4*)(sAl + off) = sl[chunk];
        }
        #pragma unroll
        for (int rep = 0; rep < 4; ++rep) {
            int idx = rep * 256 + tid;
            int nh = idx >> 9, kr = (idx >> 3) & 63, chunk = idx & 7;
            uint32_t off = (uint32_t)(kr * 128) + (((uint32_t)(chunk ^ (kr & 7))) << 4);
            const uint4* sh = (const uint4*)(Bh + (size_t)(khalf * 64 + kr) * N + n0 + nh * 64);
            const uint4* sl = (const uint4*)(Bl + (size_t)(khalf * 64 + kr) * N + n0 + nh * 64);
            *(uint4*)(sBh[nh] + off) = sh[chunk];
            *(uint4*)(sBl[nh] + off) = sl[chunk];
        }
        __syncthreads();

        #pragma unroll
        for (int s = 0; s < 4; ++s) {
            uint32_t ah[4], al[4];
            {
                int row = wm * 16 + lr16;
                uint32_t off = (uint32_t)(row * 128) + ((((uint32_t)(s * 2 + lclog) ^ (row & 7)) << 4));
                ldm_x4(ah, aAh + off);
                ldm_x4(al, aAl + off);
            }
            int rowB = s * 16 + ((lm & 1) << 3) + lr;
            uint32_t rbase = (uint32_t)(rowB * 128);
            #pragma unroll
            for (int g = 0; g < 2; ++g) {
                uint32_t chunk = (uint32_t)(((wn & 1) * 2 + g) * 2 + (lm >> 1));
                uint32_t off = rbase + ((chunk ^ (rowB & 7)) << 4);
                uint32_t bh[4], bl[4];
                ldm_x4_t(bh, aBh + off);
                ldm_x4_t(bl, aBl + off);
                mma_bf16(c[g*2],   ah, bh[0], bh[1]);
                mma_bf16(c[g*2],   ah, bl[0], bl[1]);
                mma_bf16(c[g*2],   al, bh[0], bh[1]);
                mma_bf16(c[g*2+1], ah, bh[2], bh[3]);
                mma_bf16(c[g*2+1], ah, bl[2], bl[3]);
                mma_bf16(c[g*2+1], al, bh[2], bh[3]);
            }
        }
    }

    const int rowA = m0 + wm * 16 + rq;
    const float qscale = 0.25f * 1.44269504088896f;   // hd^-1/2 * log2(e)
    #pragma unroll
    for (int t8 = 0; t8 < 4; ++t8) {
        int col = n0 + wn * 32 + t8 * 8 + d0;
        float b0 = bias[col], b1 = bias[col + 1];
        float v00 = c[t8][0] + b0, v01 = c[t8][1] + b1;
        float v10 = c[t8][2] + b0, v11 = c[t8][3] + b1;

        if (mode == 1) {
            v00 = fmaxf(v00, 0.f); v01 = fmaxf(v01, 0.f);
            v10 = fmaxf(v10, 0.f); v11 = fmaxf(v11, 0.f);
            float h00 = bfr(v00), h01 = bfr(v01), h10 = bfr(v10), h11 = bfr(v11);
            ((uint32_t*)Ch)[((size_t)rowA * 128 + col) >> 1]       = pack_bf16x2(h00, h01);
            ((uint32_t*)Cl)[((size_t)rowA * 128 + col) >> 1]       = pack_bf16x2(v00 - h00, v01 - h01);
            ((uint32_t*)Ch)[((size_t)(rowA + 8) * 128 + col) >> 1] = pack_bf16x2(h10, h11);
            ((uint32_t*)Cl)[((size_t)(rowA + 8) * 128 + col) >> 1] = pack_bf16x2(v10 - h10, v11 - h11);
        } else {
            if (n0 == 0) {
                *(float2*)(Cf + (size_t)rowA * 128 + col)       = make_float2(v00 * qscale, v01 * qscale);
                *(float2*)(Cf + (size_t)(rowA + 8) * 128 + col) = make_float2(v10 * qscale, v11 * qscale);
            } else if (n0 == 128) {
                int kc = col - 128;
                float h00 = bfr(v00), h01 = bfr(v01), h10 = bfr(v10), h11 = bfr(v11);
                ((uint32_t*)Ch)[((size_t)rowA * 128 + kc) >> 1]       = pack_bf16x2(h00, h01);
                ((uint32_t*)Cl)[((size_t)rowA * 128 + kc) >> 1]       = pack_bf16x2(v00 - h00, v01 - h01);
                ((uint32_t*)Ch)[((size_t)(rowA + 8) * 128 + kc) >> 1] = pack_bf16x2(h10, h11);
                ((uint32_t*)Cl)[((size_t)(rowA + 8) * 128 + kc) >> 1] = pack_bf16x2(v10 - h10, v11 - h11);
            } else {
                int vc = col - 256;
                ((uint32_t*)Cv)[((size_t)rowA * 128 + vc) >> 1]       = pack_bf16x2(bfr(v00), bfr(v01));
                ((uint32_t*)Cv)[((size_t)(rowA + 8) * 128 + vc) >> 1] = pack_bf16x2(bfr(v10), bfr(v11));
            }
        }
    }
}

// ============ fused ff2 GEMM + residual add + LayerNorm (BM=32, N=128) =====
#define SA_H 0
#define SA_L 4096
#define SB_H 8192
#define SB_L 24576
__global__ __launch_bounds__(256) void hmma_gemm_ln(
    const __nv_bfloat16* __restrict__ Ah, const __nv_bfloat16* __restrict__ Al,
    const __nv_bfloat16* __restrict__ Bh, const __nv_bfloat16* __restrict__ Bl,
    const float* __restrict__ bias, const float* __restrict__ xin,
    const float* __restrict__ gamma, const float* __restrict__ beta,
    float* __restrict__ out)
{
    __shared__ __align__(16) uint8_t sbuf[40960];

    const int tid  = threadIdx.x;
    const int lane = tid & 31;
    const int w    = tid >> 5;
    const int wm   = w & 1;
    const int wn   = w >> 1;
    const int m0   = blockIdx.y * 32;

    const int rq = lane >> 2;
    const int d0 = (lane & 3) * 2;
    const int lr16  = lane & 15;
    const int lclog = lane >> 4;
    const int lm = lane >> 3, lr = lane & 7;

    float c[4][4];
    #pragma unroll
    for (int i = 0; i < 4; i++)
        #pragma unroll
        for (int j = 0; j < 4; j++) c[i][j] = 0.f;

    const uint32_t aAh = smem_u32(sbuf + SA_H);
    const uint32_t aAl = smem_u32(sbuf + SA_L);
    const uint32_t aBh = smem_u32(sbuf + SB_H + (wn >> 1) * 8192);
    const uint32_t aBl = smem_u32(sbuf + SB_L + (wn >> 1) * 8192);

    #pragma unroll
    for (int khalf = 0; khalf < 2; ++khalf) {
        __syncthreads();
        {
            int row = tid >> 3, chunk = tid & 7;
            uint32_t off = (uint32_t)(row * 128) + (((uint32_t)(chunk ^ (row & 7))) << 4);
            const uint4* sh = (const uint4*)(Ah + (size_t)(m0 + row) * 128 + khalf * 64);
            const uint4* sl = (const uint4*)(Al + (size_t)(m0 + row) * 128 + khalf * 64);
            *(uint4*)(sbuf + SA_H + off) = sh[chunk];
            *(uint4*)(sbuf + SA_L + off) = sl[chunk];
        }
        #pragma unroll
        for (int rep = 0; rep < 4; ++rep) {
            int idx = rep * 256 + tid;
            int nh = idx >> 9, kr = (idx >> 3) & 63, chunk = idx & 7;
            uint32_t off = (uint32_t)(kr * 128) + (((uint32_t)(chunk ^ (kr & 7))) << 4);
            const uint4* sh = (const uint4*)(Bh + (size_t)(khalf * 64 + kr) * 128 + nh * 64);
            const uint4* sl = (const uint4*)(Bl + (size_t)(khalf * 64 + kr) * 128 + nh * 64);
            *(uint4*)(sbuf + SB_H + nh * 8192 + off) = sh[chunk];
            *(uint4*)(sbuf + SB_L + nh * 8192 + off) = sl[chunk];
        }
        __syncthreads();

        #pragma unroll
        for (int s = 0; s < 4; ++s) {
            uint32_t ah[4], al[4];
            {
                int row = wm * 16 + lr16;
                uint32_t off = (uint32_t)(row * 128) + ((((uint32_t)(s * 2 + lclog) ^ (row & 7)) << 4));
                ldm_x4(ah, aAh + off);
                ldm_x4(al, aAl + off);
            }
            int rowB = s * 16 + ((lm & 1) << 3) + lr;
            uint32_t rbase = (uint32_t)(rowB * 128);
            #pragma unroll
            for (int g = 0; g < 2; ++g) {
                uint32_t chunk = (uint32_t)(((wn & 1) * 2 + g) * 2 + (lm >> 1));
                uint32_t off = rbase + ((chunk ^ (rowB & 7)) << 4);
                uint32_t bh[4], bl[4];
                ldm_x4_t(bh, aBh + off);
                ldm_x4_t(bl, aBl + off);
                mma_bf16(c[g*2],   ah, bh[0], bh[1]);
                mma_bf16(c[g*2],   ah, bl[0], bl[1]);
                mma_bf16(c[g*2],   al, bh[0], bh[1]);
                mma_bf16(c[g*2+1], ah, bh[2], bh[3]);
                mma_bf16(c[g*2+1], ah, bl[2], bl[3]);
                mma_bf16(c[g*2+1], al, bh[2], bh[3]);
            }
        }
    }

    __syncthreads();
    float* sC = (float*)sbuf;                 // 32 x 128 fp32 = 16 KB
    {
        const int rowT = wm * 16 + rq;
        #pragma unroll
        for (int t8 = 0; t8 < 4; ++t8) {
            int col = wn * 32 + t8 * 8 + d0;
            float b0 = bias[col], b1 = bias[col + 1];
            sC[rowT * 128 + col]           = c[t8][0] + b0;
            sC[rowT * 128 + col + 1]       = c[t8][1] + b1;
            sC[(rowT + 8) * 128 + col]     = c[t8][2] + b0;
            sC[(rowT + 8) * 128 + col + 1] = c[t8][3] + b1;
        }
    }
    __syncthreads();

    {
        const int row = tid >> 3;
        const int q8 = tid & 7;
        float* vr = sC + row * 128 + q8 * 16;
        const float* xr = xin + (size_t)(m0 + row) * 128 + q8 * 16;

        float s = 0.f;
        #pragma unroll
        for (int j = 0; j < 16; j++) {
            float v = vr[j] + xr[j];
            vr[j] = v;
            s += v;
        }
        s += __shfl_xor_sync(0xffffffffu, s, 1);
        s += __shfl_xor_sync(0xffffffffu, s, 2);
        s += __shfl_xor_sync(0xffffffffu, s, 4);
        float mu = s * (1.f / 128.f);

        float q = 0.f;
        #pragma unroll
        for (int j = 0; j < 16; j++) {
            float d = vr[j] - mu;
            q += d * d;
        }
        q += __shfl_xor_sync(0xffffffffu, q, 1);
        q += __shfl_xor_sync(0xffffffffu, q, 2);
        q += __shfl_xor_sync(0xffffffffu, q, 4);
        float rs = rsqrtf(q * (1.f / 128.f) + LN_EPS);

        float* orow = out + (size_t)(m0 + row) * 128 + q8 * 16;
        #pragma unroll
        for (int j = 0; j < 16; j++) {
            orow[j] = (vr[j] - mu) * rs * gamma[q8 * 16 + j] + beta[q8 * 16 + j];
        }
    }
}

// ============ HMMA flash attention: 4 warps, NT=2, full keys, cp.async =====
#define KROWB 48
#define CHUNKB (128 * KROWB)          // 6144 per plane
#define BUFB   (3 * CHUNKB)           // 18432 per buffer

__device__ __forceinline__ void attn_stage(uint32_t sbase, int buf, int c0,
                                           int b, int h, int tid) {
    const uint32_t dbase = sbase + (uint32_t)buf * BUFB;
    const size_t src = (size_t)(b * L_ + c0 + tid) * D_ + h * HD_;
    uint32_t dk = dbase + (uint32_t)(tid * KROWB);
    cp16(dk,                    g_kh + src);
    cp16(dk + 16,               g_kh + src + 8);
    cp16(dk + CHUNKB,           g_kl + src);
    cp16(dk + CHUNKB + 16,      g_kl + src + 8);
    cp16(dk + 2 * CHUNKB,       g_vh + src);
    cp16(dk + 2 * CHUNKB + 16,  g_vh + src + 8);
}

__global__ __launch_bounds__(128) void attn_mma_kernel(float* __restrict__ ctx)
{
    __shared__ __align__(16) uint8_t sKV[2 * BUFB];   // 36 KB

    const int tid  = threadIdx.x;
    const int lane = tid & 31;
    const int w    = tid >> 5;         // 0..3, warp owns q rows w*32..+31 (2 tiles)
    const int b    = blockIdx.y >> 3;
    const int h    = blockIdx.y & 7;
    const int q0   = blockIdx.x << 7;

    const int rq = lane >> 2;
    const int d0 = (lane & 3) * 2;

    const uint32_t sbase = smem_u32(sKV);

    // ---- Q fragments (hi/lo bf16 split); Q is pre-scaled --------------------
    uint32_t ah[2][4], al[2][4];
    #pragma unroll
    for (int t = 0; t < 2; t++) {
        int rowA = q0 + w * 32 + t * 16 + rq;
        const float* qb = g_q + (size_t)(b * L_ + rowA) * D_ + h * HD_;
        float2 e0 = *(const float2*)(qb + d0);
        float2 e1 = *(const float2*)(qb + (size_t)8 * D_ + d0);
        float2 e2 = *(const float2*)(qb + d0 + 8);
        float2 e3 = *(const float2*)(qb + (size_t)8 * D_ + d0 + 8);
        float v[8] = {e0.x, e0.y, e1.x, e1.y, e2.x, e2.y, e3.x, e3.y};
        #pragma unroll
        for (int j = 0; j < 4; j++) {
            float hx = bfr(v[2*j]), hy = bfr(v[2*j+1]);
            ah[t][j] = pack_bf16x2(hx, hy);
            al[t][j] = pack_bf16x2(v[2*j] - hx, v[2*j+1] - hy);
        }
    }

    const uint4* mbase = (const uint4*)g_maskbits;
    int mrowA[2], mrowB[2];
    #pragma unroll
    for (int t = 0; t < 2; t++) {
        mrowA[t] = (b * L_ + q0 + w * 32 + t * 16 + rq) * 8;
        mrowB[t] = mrowA[t] + 8 * 8;
    }

    const int lm = lane >> 3, lr = lane & 7;
    const uint32_t kOff = (uint32_t)((((lm >> 1) << 3) + lr) * KROWB + ((lm & 1) << 4));
    const uint32_t vOff = (uint32_t)((((lm & 1) << 3) + lr) * KROWB + ((lm >> 1) << 4));

    float o[2][2][4];
    float lac[2][4];
    #pragma unroll
    for (int t = 0; t < 2; t++) {
        #pragma unroll
        for (int n = 0; n < 2; n++)
            #pragma unroll
            for (int i = 0; i < 4; i++) o[t][n][i] = 0.f;
        #pragma unroll
        for (int i = 0; i < 4; i++) lac[t][i] = 0.f;
    }

    // prologue: stage first chunk
    attn_stage(sbase, 0, 0, b, h, tid);
    CP_COMMIT();

    for (int ck = 0; ck < 8; ++ck) {
        const int c0 = ck << 7;
        const int buf = ck & 1;

        if (ck < 7) {
            attn_stage(sbase, (ck + 1) & 1, (ck + 1) << 7, b, h, tid);
            CP_COMMIT();
            asm volatile("cp.async.wait_group 1;" ::: "memory");
        } else {
            asm volatile("cp.async.wait_group 0;" ::: "memory");
        }
        __syncthreads();

        const uint32_t aKh = sbase + (uint32_t)buf * BUFB + kOff;
        const uint32_t aKl = aKh + CHUNKB;
        const uint32_t aVh = sbase + (uint32_t)buf * BUFB + 2 * CHUNKB + vOff;

        uint32_t mwa[2][4], mwb[2][4];
        #pragma unroll
        for (int t = 0; t < 2; t++) {
            uint4 a = mbase[mrowA[t] + ck];
            uint4 bq = mbase[mrowB[t] + ck];
            mwa[t][0] = a.x;  mwa[t][1] = a.y;  mwa[t][2] = a.z;  mwa[t][3] = a.w;
            mwb[t][0] = bq.x; mwb[t][1] = bq.y; mwb[t][2] = bq.z; mwb[t][3] = bq.w;
        }

        #pragma unroll
        for (int s = 0; s < 8; ++s) {
            const uint32_t so = (uint32_t)(s * 16 * KROWB);
            uint32_t kh[4], kl[4], vh[4];
            ldm_x4(kh, aKh + so);
            ldm_x4(kl, aKl + so);
            ldm_x4_t(vh, aVh + so);
            const int sh = ((s & 1) << 4) + d0;

            #pragma unroll
            for (int t = 0; t < 2; t++) {
                float cA0[4] = {0.f, 0.f, 0.f, 0.f};
                float cB0[4] = {0.f, 0.f, 0.f, 0.f};
                float cA1[4] = {0.f, 0.f, 0.f, 0.f};
                float cB1[4] = {0.f, 0.f, 0.f, 0.f};
                mma_bf16(cA0, ah[t], kh[0], kh[1]);
                mma_bf16(cB0, ah[t], kl[0], kl[1]);
                mma_bf16(cA1, ah[t], kh[2], kh[3]);
                mma_bf16(cB1, ah[t], kl[2], kl[3]);
                mma_bf16(cB0, al[t], kh[0], kh[1]);
                mma_bf16(cB1, al[t], kh[2], kh[3]);

                uint32_t wa = mwa[t][s >> 1] >> sh;
                uint32_t wb = mwb[t][s >> 1] >> sh;

                float p00 = (wa & 1u)     ? 0.f : ex2f(cA0[0] + cB0[0]);
                float p01 = (wa & 2u)     ? 0.f : ex2f(cA0[1] + cB0[1]);
                float p02 = (wb & 1u)     ? 0.f : ex2f(cA0[2] + cB0[2]);
                float p03 = (wb & 2u)     ? 0.f : ex2f(cA0[3] + cB0[3]);
                float p10 = (wa & 0x100u) ? 0.f : ex2f(cA1[0] + cB1[0]);
                float p11 = (wa & 0x200u) ? 0.f : ex2f(cA1[1] + cB1[1]);
                float p12 = (wb & 0x100u) ? 0.f : ex2f(cA1[2] + cB1[2]);
                float p13 = (wb & 0x200u) ? 0.f : ex2f(cA1[3] + cB1[3]);

                uint32_t ap[4];
                ap[0] = pack_bf16x2(p00, p01);
                ap[1] = pack_bf16x2(p02, p03);
                ap[2] = pack_bf16x2(p10, p11);
                ap[3] = pack_bf16x2(p12, p13);

                mma_bf16(o[t][0], ap, vh[0], vh[1]);
                mma_bf16(o[t][1], ap, vh[2], vh[3]);
                mma_bf16(lac[t], ap, ONES2, ONES2);
            }
        }
        __syncthreads();
    }

    // ---- epilogue: normalize (l already in every lane) and write ctx --------
    #pragma unroll
    for (int t = 0; t < 2; t++) {
        float ia = (lac[t][0] > 0.f) ? (1.f / lac[t][0]) : 0.f;
        float ib = (lac[t][2] > 0.f) ? (1.f / lac[t][2]) : 0.f;
        int rowA = q0 + w * 32 + t * 16 + rq;
        float* oA = ctx + (size_t)(b * L_ + rowA) * D_ + h * HD_;
        float* oB = oA + (size_t)8 * D_;
        #pragma unroll
        for (int n = 0; n < 2; n++) {
            *(float2*)(oA + n * 8 + d0) = make_float2(o[t][n][0] * ia, o[t][n][1] * ia);
            *(float2*)(oB + n * 8 + d0) = make_float2(o[t][n][2] * ib, o[t][n][3] * ib);
        }
    }
}

// ---------------- residual add + LayerNorm (+ emit hi/lo planes) -----------
__global__ __launch_bounds__(128) void add_ln_kernel(
    const float* __restrict__ xin, const float* __restrict__ r,
    const float* __restrict__ gamma, const float* __restrict__ beta,
    float* __restrict__ out,
    __nv_bfloat16* __restrict__ oh, __nv_bfloat16* __restrict__ ol)
{
    const int row = blockIdx.x;
    const int t = threadIdx.x;
    const int warp = t >> 5, lane = t & 31;
    __shared__ float red1[4], red2[4];

    float v = xin[(size_t)row * D_ + t] + r[(size_t)row * D_ + t];

    float s = v;
    #pragma unroll
    for (int o = 16; o; o >>= 1) s += __shfl_xor_sync(0xffffffffu, s, o);
    if (lane == 0) red1[warp] = s;
    __syncthreads();
    float mu = (red1[0] + red1[1] + red1[2] + red1[3]) * (1.f / D_);

    float c = v - mu;
    float q = c * c;
    #pragma unroll
    for (int o = 16; o; o >>= 1) q += __shfl_xor_sync(0xffffffffu, q, o);
    if (lane == 0) red2[warp] = q;
    __syncthreads();
    float var = (red2[0] + red2[1] + red2[2] + red2[3]) * (1.f / D_);

    float y = c * rsqrtf(var + LN_EPS) * gamma[t] + beta[t];
    out[(size_t)row * D_ + t] = y;
    float hy = bfr(y);
    oh[(size_t)row * D_ + t] = __float2bfloat16_rn(hy);
    ol[(size_t)row * D_ + t] = __float2bfloat16_rn(y - hy);
}

// ---------------- launch --------------------------------------------------
extern "C" void kernel_launch(void* const* d_in, const int* in_sizes, int n_in,
                              void* d_out, int out_size)
{
    const float* edge_x    = (const float*)d_in[0];
    const void*  edge_mask = d_in[1];
    const float* in_proj_w = (const float*)d_in[2];
    const float* in_proj_b = (const float*)d_in[3];
    const float* w1        = (const float*)d_in[4];
    const float* b1        = (const float*)d_in[5];
    const float* w2        = (const float*)d_in[6];
    const float* b2        = (const float*)d_in[7];
    const float* g1        = (const float*)d_in[8];
    const float* beta1     = (const float*)d_in[9];
    const float* g2        = (const float*)d_in[10];
    const float* beta2     = (const float*)d_in[11];
    float* out = (float*)d_out;

    void *p_q, *p_kh, *p_kl, *p_vh, *p_xh, *p_xl;
    void *p_wqh, *p_wql, *p_w1h, *p_w1l, *p_w2h, *p_w2l;
    void *p_f1h, *p_f1l, *p_x1h, *p_x1l;
    void *p_ctx, *p_x1;
    cudaGetSymbolAddress(&p_q,   g_q);
    cudaGetSymbolAddress(&p_kh,  g_kh);
    cudaGetSymbolAddress(&p_kl,  g_kl);
    cudaGetSymbolAddress(&p_vh,  g_vh);
    cudaGetSymbolAddress(&p_xh,  g_xh);
    cudaGetSymbolAddress(&p_xl,  g_xl);
    cudaGetSymbolAddress(&p_wqh, g_wqh);
    cudaGetSymbolAddress(&p_wql, g_wql);
    cudaGetSymbolAddress(&p_w1h, g_w1h);
    cudaGetSymbolAddress(&p_w1l, g_w1l);
    cudaGetSymbolAddress(&p_w2h, g_w2h);
    cudaGetSymbolAddress(&p_w2l, g_w2l);
    cudaGetSymbolAddress(&p_f1h, g_f1h);
    cudaGetSymbolAddress(&p_f1l, g_f1l);
    cudaGetSymbolAddress(&p_x1h, g_x1h);
    cudaGetSymbolAddress(&p_x1l, g_x1l);
    cudaGetSymbolAddress(&p_ctx, g_ctx);
    cudaGetSymbolAddress(&p_x1,  g_x1);

    // 1) mask detect + bitpack
    detect_mask_kernel<<<1, 32>>>((const unsigned char*)edge_mask);
    maskbits_kernel<<<NMASKW / 256, 256>>>(edge_mask);

    // 2) pre-convert edge_x + all weights
    conv_kernel<<<ROWS * D_ / 256, 256>>>(edge_x, (__nv_bfloat16*)p_xh, (__nv_bfloat16*)p_xl, ROWS * D_);
    conv_weights_kernel<<<320, 256>>>(in_proj_w, w1, w2);

    // 3) QKV projection (mode 2): Q fp32 pre-scaled, K hi/lo, V hi
    {
        dim3 grid(3, ROWS / 32);
        hmma_gemm_pre<<<grid, 256>>>((const __nv_bfloat16*)p_xh, (const __nv_bfloat16*)p_xl,
                                     (const __nv_bfloat16*)p_wqh, (const __nv_bfloat16*)p_wql,
                                     in_proj_b, 3 * D_, 2,
                                     (float*)p_q, (__nv_bfloat16*)p_kh, (__nv_bfloat16*)p_kl,
                                     (__nv_bfloat16*)p_vh);
    }

    // 4) masked attention -> normalized ctx (4 warps, NT=2, all keys)
    {
        dim3 grid(L_ / 128, B_ * H_);
        attn_mma_kernel<<<grid, 128>>>((float*)p_ctx);
    }

    // 5) x1 = LN(edge_x + ctx), emit fp32 + hi/lo planes
    add_ln_kernel<<<ROWS, 128>>>(edge_x, (const float*)p_ctx,
                                 g1, beta1, (float*)p_x1,
                                 (__nv_bfloat16*)p_x1h, (__nv_bfloat16*)p_x1l);

    // 6) ff1 = relu(x1 @ w1 + b1) -> hi/lo planes (mode 1)
    {
        dim3 grid(1, ROWS / 32);
        hmma_gemm_pre<<<grid, 256>>>((const __nv_bfloat16*)p_x1h, (const __nv_bfloat16*)p_x1l,
                                     (const __nv_bfloat16*)p_w1h, (const __nv_bfloat16*)p_w1l,
                                     b1, D_, 1,
                                     nullptr, (__nv_bfloat16*)p_f1h, (__nv_bfloat16*)p_f1l, nullptr);
    }
    // 7) out = LN(x1 + ff1 @ w2 + b2)  (fused GEMM + LN, BM=32)
    {
        dim3 grid(1, ROWS / 32);
        hmma_gemm_ln<<<grid, 256>>>((const __nv_bfloat16*)p_f1h, (const __nv_bfloat16*)p_f1l,
                                    (const __nv_bfloat16*)p_w2h, (const __nv_bfloat16*)p_w2l,
                                    b2, (const float*)p_x1, g2, beta2, out);
    }
}

// round 10
// speedup vs baseline: 1.0642x; 1.0222x over previous
#include <cuda_runtime.h>
#include <cuda_bf16.h>
#include <math_constants.h>
#include <cstdint>

// Problem constants
#define B_   16
#define L_   1024
#define D_   128
#define H_   8
#define HD_  16
#define ROWS (B_ * L_)          // 16384
#define LN_EPS 1e-5f
#define NMASKW (B_ * L_ * L_ / 32)

// ---------------- scratch (device globals) ---------------------------------
__device__ float g_q  [ROWS * D_];                 // Q fp32, PRE-SCALED
__device__ __nv_bfloat16 g_kh[ROWS * D_];
__device__ __nv_bfloat16 g_kl[ROWS * D_];
__device__ __nv_bfloat16 g_vh[ROWS * D_];
__device__ __nv_bfloat16 g_xh[ROWS * D_];
__device__ __nv_bfloat16 g_xl[ROWS * D_];
__device__ __nv_bfloat16 g_wqh[D_ * 3 * D_];
__device__ __nv_bfloat16 g_wql[D_ * 3 * D_];
__device__ __nv_bfloat16 g_w1h[D_ * D_];
__device__ __nv_bfloat16 g_w1l[D_ * D_];
__device__ __nv_bfloat16 g_w2h[D_ * D_];
__device__ __nv_bfloat16 g_w2l[D_ * D_];
__device__ __nv_bfloat16 g_x1h[ROWS * D_];
__device__ __nv_bfloat16 g_x1l[ROWS * D_];
__device__ float g_ctx[ROWS * D_];
__device__ float g_x1 [ROWS * D_];
__device__ uint32_t g_maskbits[NMASKW];
__device__ int g_mask_is_i32;

// ============================ helpers ======================================
__device__ __forceinline__ uint32_t smem_u32(const void* p) {
    uint32_t a;
    asm("{ .reg .u64 t; cvta.to.shared.u64 t, %1; cvt.u32.u64 %0, t; }"
        : "=r"(a) : "l"(p));
    return a;
}
__device__ __forceinline__ uint32_t pack_bf16x2(float e, float o) {
    uint32_t r;
    asm("cvt.rn.bf16x2.f32 %0, %1, %2;" : "=r"(r) : "f"(o), "f"(e));
    return r;
}
__device__ __forceinline__ float ex2f(float x) {
    float y; asm("ex2.approx.f32 %0, %1;" : "=f"(y) : "f"(x)); return y;
}
__device__ __forceinline__ float bfr(float x) {
    return __bfloat162float(__float2bfloat16_rn(x));
}
__device__ __forceinline__ void mma_bf16(float* c, const uint32_t* a, uint32_t b0, uint32_t b1) {
    asm volatile("mma.sync.aligned.m16n8k16.row.col.f32.bf16.bf16.f32 "
        "{%0,%1,%2,%3}, {%4,%5,%6,%7}, {%8,%9}, {%0,%1,%2,%3};"
        : "+f"(c[0]), "+f"(c[1]), "+f"(c[2]), "+f"(c[3])
        : "r"(a[0]), "r"(a[1]), "r"(a[2]), "r"(a[3]), "r"(b0), "r"(b1));
}
__device__ __forceinline__ void ldm_x4(uint32_t* r, uint32_t addr) {
    asm volatile("ldmatrix.sync.aligned.m8n8.x4.shared.b16 {%0,%1,%2,%3}, [%4];"
        : "=r"(r[0]), "=r"(r[1]), "=r"(r[2]), "=r"(r[3]) : "r"(addr));
}
__device__ __forceinline__ void ldm_x4_t(uint32_t* r, uint32_t addr) {
    asm volatile("ldmatrix.sync.aligned.m8n8.x4.trans.shared.b16 {%0,%1,%2,%3}, [%4];"
        : "=r"(r[0]), "=r"(r[1]), "=r"(r[2]), "=r"(r[3]) : "r"(addr));
}
__device__ __forceinline__ void cp16(uint32_t dst, const void* src) {
    asm volatile("cp.async.cg.shared.global [%0], [%1], 16;"
        :: "r"(dst), "l"(src) : "memory");
}
#define CP_COMMIT() asm volatile("cp.async.commit_group;" ::: "memory")
#define ONES2 0x3F803F80u

// ---------------- mask detect + bitpack + conversions ----------------------
__global__ void detect_mask_kernel(const unsigned char* __restrict__ m) {
    if (threadIdx.x == 0 && blockIdx.x == 0) {
        int i32like = 1;
        for (int i = 0; i < 4096; i += 4) {
            unsigned char b0 = m[i], b1 = m[i+1], b2 = m[i+2], b3 = m[i+3];
            if ((b1 | b2 | b3) != 0 || b0 > 1) { i32like = 0; break; }
        }
        g_mask_is_i32 = i32like;
    }
}
__global__ void maskbits_kernel(const void* __restrict__ in) {
    int wIdx = blockIdx.x * blockDim.x + threadIdx.x;
    if (wIdx >= NMASKW) return;
    uint32_t bits = 0;
    if (g_mask_is_i32) {
        const int* p = (const int*)in + (size_t)wIdx * 32;
        #pragma unroll
        for (int j = 0; j < 32; j++) bits |= (p[j] != 0 ? 1u : 0u) << j;
    } else {
        const uint4* p = (const uint4*)((const uint8_t*)in + (size_t)wIdx * 32);
        uint4 a = p[0], bq = p[1];
        uint32_t ww[8] = {a.x, a.y, a.z, a.w, bq.x, bq.y, bq.z, bq.w};
        #pragma unroll
        for (int u = 0; u < 8; u++)
            #pragma unroll
            for (int j = 0; j < 4; j++)
                bits |= (((ww[u] >> (8 * j)) & 0xFFu) ? 1u : 0u) << (u * 4 + j);
    }
    g_maskbits[wIdx] = bits;
}
__global__ void conv_kernel(const float* __restrict__ src,
                            __nv_bfloat16* __restrict__ dh,
                            __nv_bfloat16* __restrict__ dl, int n) {
    int i = blockIdx.x * blockDim.x + threadIdx.x;
    if (i >= n) return;
    float f = src[i];
    float h = bfr(f);
    dh[i] = __float2bfloat16_rn(h);
    dl[i] = __float2bfloat16_rn(f - h);
}
__global__ void conv_weights_kernel(const float* __restrict__ wq,
                                    const float* __restrict__ w1,
                                    const float* __restrict__ w2) {
    int i = blockIdx.x * blockDim.x + threadIdx.x;
    const float* src; __nv_bfloat16 *dh, *dl; int j;
    if (i < 49152)      { src = wq; dh = g_wqh; dl = g_wql; j = i; }
    else if (i < 65536) { src = w1; dh = g_w1h; dl = g_w1l; j = i - 49152; }
    else                { src = w2; dh = g_w2h; dl = g_w2l; j = i - 65536; }
    float f = src[j];
    float h = bfr(f);
    dh[j] = __float2bfloat16_rn(h);
    dl[j] = __float2bfloat16_rn(f - h);
}

// ============== QKV GEMM: BM=64, single-shot cp.async staging ==============
// smem: A planes [pl][kh][64 rows][128B] @0 (32KB); B planes [pl][nh][128][128B] @32768 (64KB)
#define QKV_SA 0u
#define QKV_SB 32768u
#define QKV_SMEM (96 * 1024)
__global__ __launch_bounds__(256) void qkv_gemm_kernel(const float* __restrict__ bias)
{
    extern __shared__ __align__(16) uint8_t dsm[];
    const uint32_t sbase = smem_u32(dsm);

    const int tid  = threadIdx.x;
    const int lane = tid & 31;
    const int w    = tid >> 5;
    const int wm   = w & 3;
    const int wn   = w >> 2;
    const int m0   = blockIdx.y * 64;
    const int n0   = blockIdx.x * 128;

    const int rq = lane >> 2;
    const int d0 = (lane & 3) * 2;
    const int lr16  = lane & 15;
    const int lclog = lane >> 4;
    const int lm = lane >> 3, lr = lane & 7;

    // ---- single-shot staging: A (8 lines/thr) + B (16 lines/thr) ----------
    #pragma unroll
    for (int rep = 0; rep < 8; ++rep) {
        int idx = rep * 256 + tid;                 // < 2048
        int plane = idx >> 10, kh = (idx >> 9) & 1, row = (idx >> 3) & 63, chunk = idx & 7;
        const __nv_bfloat16* src = (plane ? g_xl : g_xh)
            + (size_t)(m0 + row) * 128 + kh * 64 + chunk * 8;
        uint32_t dst = sbase + QKV_SA + (uint32_t)(plane * 16384 + kh * 8192 + row * 128
                     + (((chunk ^ (row & 7))) << 4));
        cp16(dst, src);
    }
    #pragma unroll
    for (int rep = 0; rep < 16; ++rep) {
        int idx = rep * 256 + tid;                 // < 4096
        int plane = idx >> 11, nh = (idx >> 10) & 1, kr = (idx >> 3) & 127, chunk = idx & 7;
        const __nv_bfloat16* src = (plane ? g_wql : g_wqh)
            + (size_t)kr * (3 * D_) + n0 + nh * 64 + chunk * 8;
        uint32_t dst = sbase + QKV_SB + (uint32_t)(plane * 32768 + nh * 16384 + kr * 128
                     + (((chunk ^ (kr & 7))) << 4));
        cp16(dst, src);
    }
    CP_COMMIT();

    float c[8][4];
    #pragma unroll
    for (int i = 0; i < 8; i++)
        #pragma unroll
        for (int j = 0; j < 4; j++) c[i][j] = 0.f;

    asm volatile("cp.async.wait_group 0;" ::: "memory");
    __syncthreads();

    const int rowA = wm * 16 + lr16;
    #pragma unroll
    for (int s = 0; s < 8; ++s) {
        const int kh = s >> 2, sl = s & 3;
        uint32_t ah[4], al[4];
        {
            uint32_t off = QKV_SA + (uint32_t)(kh * 8192 + rowA * 128
                         + ((((sl * 2 + lclog) ^ (rowA & 7))) << 4));
            ldm_x4(ah, sbase + off);
            ldm_x4(al, sbase + off + 16384);
        }
        int rowB = s * 16 + ((lm & 1) << 3) + lr;
        uint32_t rbase = QKV_SB + (uint32_t)(wn * 16384 + rowB * 128);
        #pragma unroll
        for (int g = 0; g < 4; ++g) {
            uint32_t chunk = (uint32_t)(g * 2 + (lm >> 1));
            uint32_t off = rbase + ((chunk ^ (rowB & 7)) << 4);
            uint32_t bh[4], bl[4];
            ldm_x4_t(bh, sbase + off);
            ldm_x4_t(bl, sbase + off + 32768);
            mma_bf16(c[g*2],   ah, bh[0], bh[1]);
            mma_bf16(c[g*2],   ah, bl[0], bl[1]);
            mma_bf16(c[g*2],   al, bh[0], bh[1]);
            mma_bf16(c[g*2+1], ah, bh[2], bh[3]);
            mma_bf16(c[g*2+1], ah, bl[2], bl[3]);
            mma_bf16(c[g*2+1], al, bh[2], bh[3]);
        }
    }

    // ---- epilogue: Q fp32 pre-scaled / K hi,lo / V hi ----------------------
    const int rowO = m0 + wm * 16 + rq;
    const float qscale = 0.25f * 1.44269504088896f;
    #pragma unroll
    for (int t8 = 0; t8 < 8; ++t8) {
        int col = n0 + wn * 64 + t8 * 8 + d0;
        float b0 = bias[col], b1 = bias[col + 1];
        float v00 = c[t8][0] + b0, v01 = c[t8][1] + b1;
        float v10 = c[t8][2] + b0, v11 = c[t8][3] + b1;

        if (n0 == 0) {
            *(float2*)(g_q + (size_t)rowO * 128 + col)       = make_float2(v00 * qscale, v01 * qscale);
            *(float2*)(g_q + (size_t)(rowO + 8) * 128 + col) = make_float2(v10 * qscale, v11 * qscale);
        } else if (n0 == 128) {
            int kc = col - 128;
            float h00 = bfr(v00), h01 = bfr(v01), h10 = bfr(v10), h11 = bfr(v11);
            ((uint32_t*)g_kh)[((size_t)rowO * 128 + kc) >> 1]       = pack_bf16x2(h00, h01);
            ((uint32_t*)g_kl)[((size_t)rowO * 128 + kc) >> 1]       = pack_bf16x2(v00 - h00, v01 - h01);
            ((uint32_t*)g_kh)[((size_t)(rowO + 8) * 128 + kc) >> 1] = pack_bf16x2(h10, h11);
            ((uint32_t*)g_kl)[((size_t)(rowO + 8) * 128 + kc) >> 1] = pack_bf16x2(v10 - h10, v11 - h11);
        } else {
            int vc = col - 256;
            ((uint32_t*)g_vh)[((size_t)rowO * 128 + vc) >> 1]       = pack_bf16x2(bfr(v00), bfr(v01));
            ((uint32_t*)g_vh)[((size_t)(rowO + 8) * 128 + vc) >> 1] = pack_bf16x2(bfr(v10), bfr(v11));
        }
    }
}

// ====== fused FFN: relu(x1@w1+b1)@w2 + b2, + residual + LayerNorm ==========
// BM=64, 256 thr. smem: A(x1) 32KB @0, T 32KB @32768, W1 64KB @65536, W2 64KB @131072
#define FFN_SA 0u
#define FFN_ST 32768u
#define FFN_SW1 65536u
#define FFN_SW2 131072u
#define FFN_SMEM (192 * 1024)
__global__ __launch_bounds__(256) void hmma_ffn_ln(
    const float* __restrict__ b1, const float* __restrict__ b2,
    const float* __restrict__ xin,
    const float* __restrict__ gamma, const float* __restrict__ beta,
    float* __restrict__ out)
{
    extern __shared__ __align__(16) uint8_t dsm[];
    const uint32_t sbase = smem_u32(dsm);

    const int tid  = threadIdx.x;
    const int lane = tid & 31;
    const int w    = tid >> 5;
    const int wm   = w & 3;
    const int wn   = w >> 2;
    const int m0   = blockIdx.x * 64;

    const int rq = lane >> 2;
    const int d0 = (lane & 3) * 2;
    const int lr16  = lane & 15;
    const int lclog = lane >> 4;
    const int lm = lane >> 3, lr = lane & 7;

    // ---- stage A (x1 planes) + W1: group 0 ---------------------------------
    #pragma unroll
    for (int rep = 0; rep < 8; ++rep) {
        int idx = rep * 256 + tid;
        int plane = idx >> 10, kh = (idx >> 9) & 1, row = (idx >> 3) & 63, chunk = idx & 7;
        const __nv_bfloat16* src = (plane ? g_x1l : g_x1h)
            + (size_t)(m0 + row) * 128 + kh * 64 + chunk * 8;
        uint32_t dst = sbase + FFN_SA + (uint32_t)(plane * 16384 + kh * 8192 + row * 128
                     + (((chunk ^ (row & 7))) << 4));
        cp16(dst, src);
    }
    #pragma unroll
    for (int rep = 0; rep < 16; ++rep) {
        int idx = rep * 256 + tid;
        int plane = idx >> 11, nh = (idx >> 10) & 1, kr = (idx >> 3) & 127, chunk = idx & 7;
        const __nv_bfloat16* src = (plane ? g_w1l : g_w1h)
            + (size_t)kr * 128 + nh * 64 + chunk * 8;
        uint32_t dst = sbase + FFN_SW1 + (uint32_t)(plane * 32768 + nh * 16384 + kr * 128
                     + (((chunk ^ (kr & 7))) << 4));
        cp16(dst, src);
    }
    CP_COMMIT();
    // ---- stage W2: group 1 (overlaps GEMM1 compute) -------------------------
    #pragma unroll
    for (int rep = 0; rep < 16; ++rep) {
        int idx = rep * 256 + tid;
        int plane = idx >> 11, nh = (idx >> 10) & 1, kr = (idx >> 3) & 127, chunk = idx & 7;
        const __nv_bfloat16* src = (plane ? g_w2l : g_w2h)
            + (size_t)kr * 128 + nh * 64 + chunk * 8;
        uint32_t dst = sbase + FFN_SW2 + (uint32_t)(plane * 32768 + nh * 16384 + kr * 128
                     + (((chunk ^ (kr & 7))) << 4));
        cp16(dst, src);
    }
    CP_COMMIT();

    float c[8][4];
    #pragma unroll
    for (int i = 0; i < 8; i++)
        #pragma unroll
        for (int j = 0; j < 4; j++) c[i][j] = 0.f;

    asm volatile("cp.async.wait_group 1;" ::: "memory");   // A + W1 ready
    __syncthreads();

    const int rowA = wm * 16 + lr16;
    // ================= GEMM1: T = relu(x1 @ w1 + b1) =========================
    #pragma unroll
    for (int s = 0; s < 8; ++s) {
        const int kh = s >> 2, sl = s & 3;
        uint32_t ah[4], al[4];
        {
            uint32_t off = FFN_SA + (uint32_t)(kh * 8192 + rowA * 128
                         + ((((sl * 2 + lclog) ^ (rowA & 7))) << 4));
            ldm_x4(ah, sbase + off);
            ldm_x4(al, sbase + off + 16384);
        }
        int rowB = s * 16 + ((lm & 1) << 3) + lr;
        uint32_t rbase = FFN_SW1 + (uint32_t)(wn * 16384 + rowB * 128);
        #pragma unroll
        for (int g = 0; g < 4; ++g) {
            uint32_t chunk = (uint32_t)(g * 2 + (lm >> 1));
            uint32_t off = rbase + ((chunk ^ (rowB & 7)) << 4);
            uint32_t bh[4], bl[4];
            ldm_x4_t(bh, sbase + off);
            ldm_x4_t(bl, sbase + off + 32768);
            mma_bf16(c[g*2],   ah, bh[0], bh[1]);
            mma_bf16(c[g*2],   ah, bl[0], bl[1]);
            mma_bf16(c[g*2],   al, bh[0], bh[1]);
            mma_bf16(c[g*2+1], ah, bh[2], bh[3]);
            mma_bf16(c[g*2+1], ah, bl[2], bl[3]);
            mma_bf16(c[g*2+1], al, bh[2], bh[3]);
        }
    }

    // ---- epilogue 1: relu + hi/lo split -> T planes in smem -----------------
    // T layout mirrors A: [plane][kh=wn][row][128B swizzled]
    {
        const int rowT = wm * 16 + rq;
        #pragma unroll
        for (int t8 = 0; t8 < 8; ++t8) {
            int col = wn * 64 + t8 * 8 + d0;      // global T col; kh = wn
            float bb0 = b1[col], bb1 = b1[col + 1];
            float v00 = fmaxf(c[t8][0] + bb0, 0.f), v01 = fmaxf(c[t8][1] + bb1, 0.f);
            float v10 = fmaxf(c[t8][2] + bb0, 0.f), v11 = fmaxf(c[t8][3] + bb1, 0.f);
            float h00 = bfr(v00), h01 = bfr(v01), h10 = bfr(v10), h11 = bfr(v11);
            uint32_t off0 = FFN_ST + (uint32_t)(wn * 8192 + rowT * 128
                          + (((t8 ^ (rowT & 7))) << 4) + d0 * 2);
            uint32_t off1 = FFN_ST + (uint32_t)(wn * 8192 + (rowT + 8) * 128
                          + (((t8 ^ ((rowT + 8) & 7))) << 4) + d0 * 2);
            *(uint32_t*)(dsm + off0)           = pack_bf16x2(h00, h01);
            *(uint32_t*)(dsm + off0 + 16384)   = pack_bf16x2(v00 - h00, v01 - h01);
            *(uint32_t*)(dsm + off1)           = pack_bf16x2(h10, h11);
            *(uint32_t*)(dsm + off1 + 16384)   = pack_bf16x2(v10 - h10, v11 - h11);
        }
    }
    asm volatile("cp.async.wait_group 0;" ::: "memory");   // W2 ready
    __syncthreads();

    // ================= GEMM2: Y = T @ w2 =====================================
    #pragma unroll
    for (int i = 0; i < 8; i++)
        #pragma unroll
        for (int j = 0; j < 4; j++) c[i][j] = 0.f;

    #pragma unroll
    for (int s = 0; s < 8; ++s) {
        const int kh = s >> 2, sl = s & 3;
        uint32_t ah[4], al[4];
        {
            uint32_t off = FFN_ST + (uint32_t)(kh * 8192 + rowA * 128
                         + ((((sl * 2 + lclog) ^ (rowA & 7))) << 4));
            ldm_x4(ah, sbase + off);
            ldm_x4(al, sbase + off + 16384);
        }
        int rowB = s * 16 + ((lm & 1) << 3) + lr;
        uint32_t rbase = FFN_SW2 + (uint32_t)(wn * 16384 + rowB * 128);
        #pragma unroll
        for (int g = 0; g < 4; ++g) {
            uint32_t chunk = (uint32_t)(g * 2 + (lm >> 1));
            uint32_t off = rbase + ((chunk ^ (rowB & 7)) << 4);
            uint32_t bh[4], bl[4];
            ldm_x4_t(bh, sbase + off);
            ldm_x4_t(bl, sbase + off + 32768);
            mma_bf16(c[g*2],   ah, bh[0], bh[1]);
            mma_bf16(c[g*2],   ah, bl[0], bl[1]);
            mma_bf16(c[g*2],   al, bh[0], bh[1]);
            mma_bf16(c[g*2+1], ah, bh[2], bh[3]);
            mma_bf16(c[g*2+1], ah, bl[2], bl[3]);
            mma_bf16(c[g*2+1], al, bh[2], bh[3]);
        }
    }

    // ---- epilogue 2: +b2 -> sC (overlay on W1), residual + LN ---------------
    __syncthreads();
    float* sC = (float*)(dsm + FFN_SW1);        // 64 x 128 fp32 = 32 KB
    {
        const int rowT = wm * 16 + rq;
        #pragma unroll
        for (int t8 = 0; t8 < 8; ++t8) {
            int col = wn * 64 + t8 * 8 + d0;
            float bb0 = b2[col], bb1 = b2[col + 1];
            sC[rowT * 128 + col]           = c[t8][0] + bb0;
            sC[rowT * 128 + col + 1]       = c[t8][1] + bb1;
            sC[(rowT + 8) * 128 + col]     = c[t8][2] + bb0;
            sC[(rowT + 8) * 128 + col + 1] = c[t8][3] + bb1;
        }
    }
    __syncthreads();

    {
        const int row = tid >> 2;             // 64 rows, 4 threads/row
        const int q4 = tid & 3;
        float* vr = sC + row * 128 + q4 * 32;
        const float* xr = xin + (size_t)(m0 + row) * 128 + q4 * 32;

        float s = 0.f;
        #pragma unroll
        for (int j = 0; j < 32; j++) {
            float v = vr[j] + xr[j];
            vr[j] = v;
            s += v;
        }
        s += __shfl_xor_sync(0xffffffffu, s, 1);
        s += __shfl_xor_sync(0xffffffffu, s, 2);
        float mu = s * (1.f / 128.f);

        float q = 0.f;
        #pragma unroll
        for (int j = 0; j < 32; j++) {
            float d = vr[j] - mu;
            q += d * d;
        }
        q += __shfl_xor_sync(0xffffffffu, q, 1);
        q += __shfl_xor_sync(0xffffffffu, q, 2);
        float rs = rsqrtf(q * (1.f / 128.f) + LN_EPS);

        float* orow = out + (size_t)(m0 + row) * 128 + q4 * 32;
        #pragma unroll
        for (int j = 0; j < 32; j++) {
            orow[j] = (vr[j] - mu) * rs * gamma[q4 * 32 + j] + beta[q4 * 32 + j];
        }
    }
}

// ============ HMMA flash attention: 4 warps, NT=2, full keys, cp.async =====
#define KROWB 48
#define CHUNKB (128 * KROWB)
#define BUFB   (3 * CHUNKB)

__device__ __forceinline__ void attn_stage(uint32_t sbase, int buf, int c0,
                                           int b, int h, int tid) {
    const uint32_t dbase = sbase + (uint32_t)buf * BUFB;
    const size_t src = (size_t)(b * L_ + c0 + tid) * D_ + h * HD_;
    uint32_t dk = dbase + (uint32_t)(tid * KROWB);
    cp16(dk,                    g_kh + src);
    cp16(dk + 16,               g_kh + src + 8);
    cp16(dk + CHUNKB,           g_kl + src);
    cp16(dk + CHUNKB + 16,      g_kl + src + 8);
    cp16(dk + 2 * CHUNKB,       g_vh + src);
    cp16(dk + 2 * CHUNKB + 16,  g_vh + src + 8);
}

__global__ __launch_bounds__(128) void attn_mma_kernel(float* __restrict__ ctx)
{
    __shared__ __align__(16) uint8_t sKV[2 * BUFB];   // 36 KB

    const int tid  = threadIdx.x;
    const int lane = tid & 31;
    const int w    = tid >> 5;
    const int b    = blockIdx.y >> 3;
    const int h    = blockIdx.y & 7;
    const int q0   = blockIdx.x << 7;

    const int rq = lane >> 2;
    const int d0 = (lane & 3) * 2;

    const uint32_t sbase = smem_u32(sKV);

    uint32_t ah[2][4], al[2][4];
    #pragma unroll
    for (int t = 0; t < 2; t++) {
        int rowA = q0 + w * 32 + t * 16 + rq;
        const float* qb = g_q + (size_t)(b * L_ + rowA) * D_ + h * HD_;
        float2 e0 = *(const float2*)(qb + d0);
        float2 e1 = *(const float2*)(qb + (size_t)8 * D_ + d0);
        float2 e2 = *(const float2*)(qb + d0 + 8);
        float2 e3 = *(const float2*)(qb + (size_t)8 * D_ + d0 + 8);
        float v[8] = {e0.x, e0.y, e1.x, e1.y, e2.x, e2.y, e3.x, e3.y};
        #pragma unroll
        for (int j = 0; j < 4; j++) {
            float hx = bfr(v[2*j]), hy = bfr(v[2*j+1]);
            ah[t][j] = pack_bf16x2(hx, hy);
            al[t][j] = pack_bf16x2(v[2*j] - hx, v[2*j+1] - hy);
        }
    }

    const uint4* mbase = (const uint4*)g_maskbits;
    int mrowA[2], mrowB[2];
    #pragma unroll
    for (int t = 0; t < 2; t++) {
        mrowA[t] = (b * L_ + q0 + w * 32 + t * 16 + rq) * 8;
        mrowB[t] = mrowA[t] + 8 * 8;
    }

    const int lm = lane >> 3, lr = lane & 7;
    const uint32_t kOff = (uint32_t)((((lm >> 1) << 3) + lr) * KROWB + ((lm & 1) << 4));
    const uint32_t vOff = (uint32_t)((((lm & 1) << 3) + lr) * KROWB + ((lm >> 1) << 4));

    float o[2][2][4];
    float lac[2][4];
    #pragma unroll
    for (int t = 0; t < 2; t++) {
        #pragma unroll
        for (int n = 0; n < 2; n++)
            #pragma unroll
            for (int i = 0; i < 4; i++) o[t][n][i] = 0.f;
        #pragma unroll
        for (int i = 0; i < 4; i++) lac[t][i] = 0.f;
    }

    attn_stage(sbase, 0, 0, b, h, tid);
    CP_COMMIT();

    for (int ck = 0; ck < 8; ++ck) {
        const int buf = ck & 1;

        if (ck < 7) {
            attn_stage(sbase, (ck + 1) & 1, (ck + 1) << 7, b, h, tid);
            CP_COMMIT();
            asm volatile("cp.async.wait_group 1;" ::: "memory");
        } else {
            asm volatile("cp.async.wait_group 0;" ::: "memory");
        }
        __syncthreads();

        const uint32_t aKh = sbase + (uint32_t)buf * BUFB + kOff;
        const uint32_t aKl = aKh + CHUNKB;
        const uint32_t aVh = sbase + (uint32_t)buf * BUFB + 2 * CHUNKB + vOff;

        uint32_t mwa[2][4], mwb[2][4];
        #pragma unroll
        for (int t = 0; t < 2; t++) {
            uint4 a = mbase[mrowA[t] + ck];
            uint4 bq = mbase[mrowB[t] + ck];
            mwa[t][0] = a.x;  mwa[t][1] = a.y;  mwa[t][2] = a.z;  mwa[t][3] = a.w;
            mwb[t][0] = bq.x; mwb[t][1] = bq.y; mwb[t][2] = bq.z; mwb[t][3] = bq.w;
        }

        #pragma unroll
        for (int s = 0; s < 8; ++s) {
            const uint32_t so = (uint32_t)(s * 16 * KROWB);
            uint32_t kh[4], kl[4], vh[4];
            ldm_x4(kh, aKh + so);
            ldm_x4(kl, aKl + so);
            ldm_x4_t(vh, aVh + so);
            const int sh = ((s & 1) << 4) + d0;

            #pragma unroll
            for (int t = 0; t < 2; t++) {
                float cA0[4] = {0.f, 0.f, 0.f, 0.f};
                float cB0[4] = {0.f, 0.f, 0.f, 0.f};
                float cA1[4] = {0.f, 0.f, 0.f, 0.f};
                float cB1[4] = {0.f, 0.f, 0.f, 0.f};
                mma_bf16(cA0, ah[t], kh[0], kh[1]);
                mma_bf16(cB0, ah[t], kl[0], kl[1]);
                mma_bf16(cA1, ah[t], kh[2], kh[3]);
                mma_bf16(cB1, ah[t], kl[2], kl[3]);
                mma_bf16(cB0, al[t], kh[0], kh[1]);
                mma_bf16(cB1, al[t], kh[2], kh[3]);

                uint32_t wa = mwa[t][s >> 1] >> sh;
                uint32_t wb = mwb[t][s >> 1] >> sh;

                float p00 = (wa & 1u)     ? 0.f : ex2f(cA0[0] + cB0[0]);
                float p01 = (wa & 2u)     ? 0.f : ex2f(cA0[1] + cB0[1]);
                float p02 = (wb & 1u)     ? 0.f : ex2f(cA0[2] + cB0[2]);
                float p03 = (wb & 2u)     ? 0.f : ex2f(cA0[3] + cB0[3]);
                float p10 = (wa & 0x100u) ? 0.f : ex2f(cA1[0] + cB1[0]);
                float p11 = (wa & 0x200u) ? 0.f : ex2f(cA1[1] + cB1[1]);
                float p12 = (wb & 0x100u) ? 0.f : ex2f(cA1[2] + cB1[2]);
                float p13 = (wb & 0x200u) ? 0.f : ex2f(cA1[3] + cB1[3]);

                uint32_t ap[4];
                ap[0] = pack_bf16x2(p00, p01);
                ap[1] = pack_bf16x2(p02, p03);
                ap[2] = pack_bf16x2(p10, p11);
                ap[3] = pack_bf16x2(p12, p13);

                mma_bf16(o[t][0], ap, vh[0], vh[1]);
                mma_bf16(o[t][1], ap, vh[2], vh[3]);
                mma_bf16(lac[t], ap, ONES2, ONES2);
            }
        }
        __syncthreads();
    }

    #pragma unroll
    for (int t = 0; t < 2; t++) {
        float ia = (lac[t][0] > 0.f) ? (1.f / lac[t][0]) : 0.f;
        float ib = (lac[t][2] > 0.f) ? (1.f / lac[t][2]) : 0.f;
        int rowA = q0 + w * 32 + t * 16 + rq;
        float* oA = ctx + (size_t)(b * L_ + rowA) * D_ + h * HD_;
        float* oB = oA + (size_t)8 * D_;
        #pragma unroll
        for (int n = 0; n < 2; n++) {
            *(float2*)(oA + n * 8 + d0) = make_float2(o[t][n][0] * ia, o[t][n][1] * ia);
            *(float2*)(oB + n * 8 + d0) = make_float2(o[t][n][2] * ib, o[t][n][3] * ib);
        }
    }
}

// ---------------- residual add + LayerNorm (+ emit hi/lo planes) -----------
__global__ __launch_bounds__(128) void add_ln_kernel(
    const float* __restrict__ xin, const float* __restrict__ r,
    const float* __restrict__ gamma, const float* __restrict__ beta,
    float* __restrict__ out,
    __nv_bfloat16* __restrict__ oh, __nv_bfloat16* __restrict__ ol)
{
    const int row = blockIdx.x;
    const int t = threadIdx.x;
    const int warp = t >> 5, lane = t & 31;
    __shared__ float red1[4], red2[4];

    float v = xin[(size_t)row * D_ + t] + r[(size_t)row * D_ + t];

    float s = v;
    #pragma unroll
    for (int o = 16; o; o >>= 1) s += __shfl_xor_sync(0xffffffffu, s, o);
    if (lane == 0) red1[warp] = s;
    __syncthreads();
    float mu = (red1[0] + red1[1] + red1[2] + red1[3]) * (1.f / D_);

    float c = v - mu;
    float q = c * c;
    #pragma unroll
    for (int o = 16; o; o >>= 1) q += __shfl_xor_sync(0xffffffffu, q, o);
    if (lane == 0) red2[warp] = q;
    __syncthreads();
    float var = (red2[0] + red2[1] + red2[2] + red2[3]) * (1.f / D_);

    float y = c * rsqrtf(var + LN_EPS) * gamma[t] + beta[t];
    out[(size_t)row * D_ + t] = y;
    float hy = bfr(y);
    oh[(size_t)row * D_ + t] = __float2bfloat16_rn(hy);
    ol[(size_t)row * D_ + t] = __float2bfloat16_rn(y - hy);
}

// ---------------- launch --------------------------------------------------
extern "C" void kernel_launch(void* const* d_in, const int* in_sizes, int n_in,
                              void* d_out, int out_size)
{
    const float* edge_x    = (const float*)d_in[0];
    const void*  edge_mask = d_in[1];
    const float* in_proj_w = (const float*)d_in[2];
    const float* in_proj_b = (const float*)d_in[3];
    const float* w1        = (const float*)d_in[4];
    const float* b1        = (const float*)d_in[5];
    const float* w2        = (const float*)d_in[6];
    const float* b2        = (const float*)d_in[7];
    const float* g1        = (const float*)d_in[8];
    const float* beta1     = (const float*)d_in[9];
    const float* g2        = (const float*)d_in[10];
    const float* beta2     = (const float*)d_in[11];
    float* out = (float*)d_out;

    // allow large dynamic smem (idempotent; host-side attr, not captured)
    cudaFuncSetAttribute(qkv_gemm_kernel, cudaFuncAttributeMaxDynamicSharedMemorySize, QKV_SMEM);
    cudaFuncSetAttribute(hmma_ffn_ln,     cudaFuncAttributeMaxDynamicSharedMemorySize, FFN_SMEM);

    void *p_xh, *p_xl, *p_x1h, *p_x1l, *p_ctx, *p_x1;
    cudaGetSymbolAddress(&p_xh,  g_xh);
    cudaGetSymbolAddress(&p_xl,  g_xl);
    cudaGetSymbolAddress(&p_x1h, g_x1h);
    cudaGetSymbolAddress(&p_x1l, g_x1l);
    cudaGetSymbolAddress(&p_ctx, g_ctx);
    cudaGetSymbolAddress(&p_x1,  g_x1);

    // 1) mask detect + bitpack
    detect_mask_kernel<<<1, 32>>>((const unsigned char*)edge_mask);
    maskbits_kernel<<<NMASKW / 256, 256>>>(edge_mask);

    // 2) pre-convert edge_x + all weights
    conv_kernel<<<ROWS * D_ / 256, 256>>>(edge_x, (__nv_bfloat16*)p_xh, (__nv_bfloat16*)p_xl, ROWS * D_);
    conv_weights_kernel<<<320, 256>>>(in_proj_w, w1, w2);

    // 3) QKV projection: Q fp32 pre-scaled, K hi/lo, V hi (single-shot staging)
    {
        dim3 grid(3, ROWS / 64);
        qkv_gemm_kernel<<<grid, 256, QKV_SMEM>>>(in_proj_b);
    }

    // 4) masked attention -> normalized ctx
    {
        dim3 grid(L_ / 128, B_ * H_);
        attn_mma_kernel<<<grid, 128>>>((float*)p_ctx);
    }

    // 5) x1 = LN(edge_x + ctx), emit fp32 + hi/lo planes
    add_ln_kernel<<<ROWS, 128>>>(edge_x, (const float*)p_ctx,
                                 g1, beta1, (float*)p_x1,
                                 (__nv_bfloat16*)p_x1h, (__nv_bfloat16*)p_x1l);

    // 6) fused FFN: out = LN(x1 + relu(x1@w1+b1)@w2 + b2)
    hmma_ffn_ln<<<ROWS / 64, 256, FFN_SMEM>>>(b1, b2, (const float*)p_x1, g2, beta2, out);
}